// round 8
// baseline (speedup 1.0000x reference)
#include <cuda_runtime.h>
#include <cuda_fp16.h>
#include <cstdint>

#define BB 1024
#define TT 256
#define HH 256
#define OUTD 9
#define PL 16
#define INPAD 272   // 9 + 256 = 265, padded to 272

typedef unsigned long long u64;

// ---------------- device scratch ----------------
__device__ __align__(16) float g_reprs[BB * TT * 3];
__device__ __align__(16) float g_enc[(size_t)BB * TT * HH];
__device__ __align__(16) float g_eproj[(size_t)BB * TT * HH];
__device__ __align__(16) __half g_hx[2][BB * HH];     // fp16 hi of h (MMA input)
__device__ __align__(16) __half g_hxlo[2][BB * HH];   // fp16 lo residual of h
__device__ __align__(16) float g_h1[BB * HH];         // final encoder h (fp32)
__device__ __align__(16) float g_hd[2][BB * HH];
__device__ __align__(16) float g_dproj[BB * HH];
__device__ __align__(16) float g_ts[BB * TT];
__device__ __align__(16) float g_tw[BB * TT];
__device__ __align__(16) float g_inp[BB * INPAD];
__device__ __align__(16) float g_wihp[768 * INPAD];
__device__ __align__(16) float g_wtd[HH * HH];
__device__ __align__(16) float g_wte[HH * HH];
__device__ unsigned g_barcnt[16];

// ---------------- math helpers ----------------
__device__ __forceinline__ float ex2f(float x) {
    float r; asm("ex2.approx.f32 %0, %1;" : "=f"(r) : "f"(x)); return r;
}
__device__ __forceinline__ float frcp(float x) {
    float r; asm("rcp.approx.f32 %0, %1;" : "=f"(r) : "f"(x)); return r;
}
__device__ __forceinline__ float sigf(float x) {
    return frcp(1.0f + ex2f(-1.4426950408889634f * x));
}
__device__ __forceinline__ float tanhf_fast(float x) {
    float ax = fabsf(x);
    float e = ex2f(-2.8853900817779268f * ax);
    float r = (1.0f - e) * frcp(1.0f + e);
    return copysignf(r, x);
}
__device__ __forceinline__ u64 pack2(float lo, float hi) {
    u64 r;
    asm("mov.b64 %0, {%1, %2};" : "=l"(r)
        : "r"(__float_as_uint(lo)), "r"(__float_as_uint(hi)));
    return r;
}
__device__ __forceinline__ void unpack2(u64 v, float& lo, float& hi) {
    unsigned a, b;
    asm("mov.b64 {%0, %1}, %2;" : "=r"(a), "=r"(b) : "l"(v));
    lo = __uint_as_float(a); hi = __uint_as_float(b);
}
__device__ __forceinline__ void fma2(u64& d, u64 a, u64 b) {
    asm("fma.rn.f32x2 %0, %1, %2, %0;" : "+l"(d) : "l"(a), "l"(b));
}
__device__ __forceinline__ float warp_sum(float v) {
#pragma unroll
    for (int o = 16; o > 0; o >>= 1) v += __shfl_xor_sync(0xffffffffu, v, o);
    return v;
}
__device__ __forceinline__ unsigned ld_acq(const unsigned* p) {
    unsigned v;
    asm volatile("ld.acquire.gpu.u32 %0, [%1];" : "=r"(v) : "l"(p));
    return v;
}
__device__ __forceinline__ void red_release_add(unsigned* p, unsigned v) {
    asm volatile("red.release.gpu.global.add.u32 [%0], %1;" :: "l"(p), "r"(v) : "memory");
}
__device__ __forceinline__ uint32_t smem_u32(const void* p) {
    uint32_t a;
    asm("{ .reg .u64 t; cvta.to.shared.u64 t, %1; cvt.u32.u64 %0, t; }"
        : "=r"(a) : "l"(p));
    return a;
}
__device__ __forceinline__ void ldm4(uint32_t* r, uint32_t addr) {
    asm volatile("ldmatrix.sync.aligned.m8n8.x4.shared.b16 {%0,%1,%2,%3}, [%4];"
        : "=r"(r[0]), "=r"(r[1]), "=r"(r[2]), "=r"(r[3]) : "r"(addr));
}
__device__ __forceinline__ void mma16816(float* c,
        uint32_t a0, uint32_t a1, uint32_t a2, uint32_t a3,
        uint32_t b0, uint32_t b1) {
    asm volatile(
        "mma.sync.aligned.m16n8k16.row.col.f32.f16.f16.f32 "
        "{%0,%1,%2,%3}, {%4,%5,%6,%7}, {%8,%9}, {%0,%1,%2,%3};"
        : "+f"(c[0]), "+f"(c[1]), "+f"(c[2]), "+f"(c[3])
        : "r"(a0), "r"(a1), "r"(a2), "r"(a3), "r"(b0), "r"(b1));
}

// ---------------- init ----------------
__global__ void init_a_kernel(const float* __restrict__ x) {
    int idx = blockIdx.x * blockDim.x + threadIdx.x;
    int stride = gridDim.x * blockDim.x;
    if (idx < 16) g_barcnt[idx] = 0u;
    for (int i = idx; i < BB * INPAD; i += stride) {
        int b = i / INPAD, c = i - b * INPAD;
        g_inp[i] = (c < OUTD) ? x[((size_t)b * TT + (TT - 1)) * OUTD + c] : 0.0f;
    }
}
__global__ void init_b_kernel(const float* __restrict__ dWih,
                              const float* __restrict__ Wt) {
    int idx = blockIdx.x * blockDim.x + threadIdx.x;
    int stride = gridDim.x * blockDim.x;
    for (int i = idx; i < 768 * INPAD; i += stride) {
        int row = i / INPAD, c = i - row * INPAD;
        g_wihp[i] = (c < OUTD + HH) ? dWih[row * (OUTD + HH) + c] : 0.0f;
    }
    for (int i = idx; i < HH * HH; i += stride) {
        int g = i >> 8, c = i & 255;
        g_wtd[i] = Wt[g * (2 * HH) + c];
        g_wte[i] = Wt[g * (2 * HH) + HH + c];
    }
}

// ---------------- stage 1: agent attention ----------------
__global__ __launch_bounds__(256) void agent_attn_kernel(
        const float* __restrict__ x, const float* __restrict__ Wa,
        const float* __restrict__ ba, const float* __restrict__ va) {
    __shared__ float Was[HH * 3];
    __shared__ float vas[HH];
    __shared__ float bas[HH];
    int tid = threadIdx.x;
    for (int i = tid; i < HH * 3; i += 256) Was[i] = Wa[i];
    vas[tid] = va[tid];
    bas[tid] = ba[tid];
    __syncthreads();

    int pair = blockIdx.x * 8 + (tid >> 5);
    int lane = tid & 31;
    const float* xp = &x[(size_t)pair * 9];
    float xv[9];
#pragma unroll
    for (int i = 0; i < 9; i++) xv[i] = xp[i];

    float sc[3];
#pragma unroll
    for (int a = 0; a < 3; a++) {
        float s = 0.0f;
        float x0 = xv[a * 3], x1 = xv[a * 3 + 1], x2 = xv[a * 3 + 2];
#pragma unroll
        for (int i = 0; i < 8; i++) {
            int h = lane + 32 * i;
            float e = tanhf_fast(fmaf(x2, Was[h * 3 + 2],
                          fmaf(x1, Was[h * 3 + 1], x0 * Was[h * 3])) + bas[h]);
            s += e * vas[h];
        }
        sc[a] = warp_sum(s);
    }
    float m = fmaxf(sc[0], fmaxf(sc[1], sc[2]));
    float e0 = ex2f((sc[0] - m) * 1.4426950408889634f);
    float e1 = ex2f((sc[1] - m) * 1.4426950408889634f);
    float e2 = ex2f((sc[2] - m) * 1.4426950408889634f);
    float inv = frcp(e0 + e1 + e2);
    float a0 = e0 * inv, a1 = e1 * inv, a2 = e2 * inv;
    if (lane < 3) {
        g_reprs[pair * 3 + lane] =
            a0 * xv[lane] + a1 * xv[3 + lane] + a2 * xv[6 + lane];
    }
}

// ---------------- stage 2: mma.sync persistent encoder ----------------
// 128 CTAs = 16 batch-groups (64 rows) x 8 h-groups (32 h x 3 gates).
// gh[64,96] = h[64,256] x Whh_slice[96,256]^T via m16n8k16 HMMA;
// split precision: h = hi+lo fp16, W = hi+lo fp16, 3 product terms.
#define ROWB 528                          // padded row bytes (264 halves)
#define AHI_OFF 0
#define ALO_OFF (64 * ROWB)
#define BHI_OFF (2 * 64 * ROWB)
#define BLO_OFF (BHI_OFF + 96 * ROWB)
#define GHS_OFF (BHI_OFF + 2 * 96 * ROWB)
#define XS_OFF  (GHS_OFF + 64 * 100 * 4)
#define WIH_OFF (XS_OFF + 192 * 4)
#define BIH_OFF (WIH_OFF + 288 * 4)
#define BHH_OFF (BIH_OFF + 96 * 4)
#define ENC_SMEM (BHH_OFF + 96 * 4)

__global__ __launch_bounds__(256, 1) void enc_persistent(
        const float* __restrict__ Whh, const float* __restrict__ Wih,
        const float* __restrict__ bih, const float* __restrict__ bhh) {
    extern __shared__ __align__(16) char smraw[];
    uint32_t smem_base = smem_u32(smraw);
    float* ghs  = (float*)(smraw + GHS_OFF);      // [64][100]
    float* Xs   = (float*)(smraw + XS_OFF);       // [64][3]
    float* wihs = (float*)(smraw + WIH_OFF);      // [3*32][3]
    float* bihs = (float*)(smraw + BIH_OFF);      // [96]
    float* bhhs = (float*)(smraw + BHH_OFF);      // [96]

    int tid = threadIdx.x;
    int wid = tid >> 5, lane = tid & 31;
    int bid = blockIdx.x;
    int bg  = bid >> 3;                // batch group 0..15
    int bm0 = bg * 64;
    int hb0 = (bid & 7) * 32;

    // ---- zero A tiles (t=0 uses h=0; pad stays 0 forever) ----
    for (int i = tid; i < (2 * 64 * ROWB) / 16; i += 256)
        ((uint4*)smraw)[i] = make_uint4(0, 0, 0, 0);

    // ---- stage Whh slice fp16 hi/lo (rows n = g*32+hh, k-contig, padded) ----
    for (int i = tid; i < 96 * 128; i += 256) {
        int n = i >> 7, kp = i & 127;
        int g = n >> 5, hh = n & 31;
        float2 w = *(const float2*)&Whh[(size_t)(g * HH + hb0 + hh) * HH + kp * 2];
        __half hx0 = __float2half_rn(w.x), hx1 = __float2half_rn(w.y);
        __half lx0 = __float2half_rn(w.x - __half2float(hx0));
        __half lx1 = __float2half_rn(w.y - __half2float(hx1));
        *(__half2*)(smraw + BHI_OFF + n * ROWB + kp * 4) = __halves2half2(hx0, hx1);
        *(__half2*)(smraw + BLO_OFF + n * ROWB + kp * 4) = __halves2half2(lx0, lx1);
    }
    for (int i = tid; i < 288; i += 256) {
        int g = i / 96, r = i % 96, hh = r / 3, f = r % 3;
        wihs[(g * 32 + hh) * 3 + f] = Wih[(size_t)(g * HH + hb0 + hh) * 3 + f];
    }
    if (tid < 96) {
        int g = tid >> 5, hh = tid & 31;
        bihs[g * 32 + hh] = bih[g * HH + hb0 + hh];
        bhhs[g * 32 + hh] = bhh[g * HH + hb0 + hh];
    }
    __syncthreads();

    // warp tile: mw in 0..3 (m = mw*16), nw in 0..1 (n = nw*48)
    int mw = wid >> 1, nw = wid & 1;
    // ldmatrix per-lane address offsets
    uint32_t a_off = (uint32_t)(((lane & 7) + ((lane >> 3) & 1) * 8) * ROWB
                                + ((lane >> 4) & 1) * 16);
    uint32_t b_off = (uint32_t)(((lane & 7) + ((lane >> 4) & 1) * 8) * ROWB
                                + ((lane >> 3) & 1) * 16);
    uint32_t Ah = smem_base + AHI_OFF + mw * 16 * ROWB + a_off;
    uint32_t Al = smem_base + ALO_OFF + mw * 16 * ROWB + a_off;
    uint32_t Bh = smem_base + BHI_OFF + nw * 48 * ROWB + b_off;
    uint32_t Bl = smem_base + BLO_OFF + nw * 48 * ROWB + b_off;

    // epilogue thread mapping: row b_loc, 8 h each
    int b_loc = tid >> 2;
    int h0 = (tid & 3) * 8;
    int bglob = bm0 + b_loc;
    float hprev[8];
#pragma unroll
    for (int j = 0; j < 8; j++) hprev[j] = 0.0f;

    for (int t = 0; t < TT; t++) {
        // ---- stage A = h_{t-1} hi/lo fp16 into padded tiles ----
        if (t > 0) {
            const __half* hsrc = g_hx[(t + 1) & 1];
            const __half* lsrc = g_hxlo[(t + 1) & 1];
            for (int i = tid; i < 2048; i += 256) {
                int r = i >> 5, kc = i & 31;    // row, 8-half chunk
                uint4 v = __ldcg((const uint4*)&hsrc[(size_t)(bm0 + r) * HH + kc * 8]);
                *(uint4*)(smraw + AHI_OFF + r * ROWB + kc * 16) = v;
                uint4 u = __ldcg((const uint4*)&lsrc[(size_t)(bm0 + r) * HH + kc * 8]);
                *(uint4*)(smraw + ALO_OFF + r * ROWB + kc * 16) = u;
            }
        }
        if (tid < 192) {
            int b = tid / 3, f = tid % 3;
            Xs[b * 3 + f] = g_reprs[((size_t)(bm0 + b) * TT + t) * 3 + f];
        }
        __syncthreads();

        // ---- MMA mainloop: 16 k-chunks ----
        float acc[6][4];
#pragma unroll
        for (int f = 0; f < 6; f++)
#pragma unroll
            for (int q = 0; q < 4; q++) acc[f][q] = 0.0f;

#pragma unroll 4
        for (int ks = 0; ks < 16; ks++) {
            uint32_t koff = ks * 32;
            uint32_t ah[4], al[4], bh[3][4], bl[3][4];
            ldm4(ah, Ah + koff);
            ldm4(al, Al + koff);
#pragma unroll
            for (int f = 0; f < 3; f++) {
                ldm4(bh[f], Bh + f * 16 * ROWB + koff);
                ldm4(bl[f], Bl + f * 16 * ROWB + koff);
            }
#pragma unroll
            for (int f = 0; f < 3; f++) {
                mma16816(acc[2 * f],     ah[0], ah[1], ah[2], ah[3], bh[f][0], bh[f][1]);
                mma16816(acc[2 * f],     al[0], al[1], al[2], al[3], bh[f][0], bh[f][1]);
                mma16816(acc[2 * f],     ah[0], ah[1], ah[2], ah[3], bl[f][0], bl[f][1]);
                mma16816(acc[2 * f + 1], ah[0], ah[1], ah[2], ah[3], bh[f][2], bh[f][3]);
                mma16816(acc[2 * f + 1], al[0], al[1], al[2], al[3], bh[f][2], bh[f][3]);
                mma16816(acc[2 * f + 1], ah[0], ah[1], ah[2], ah[3], bl[f][2], bl[f][3]);
            }
        }

        // ---- scatter gh fragments to smem ----
        {
            int mrow = mw * 16 + (lane >> 2);
            int ncol = nw * 48 + 2 * (lane & 3);
#pragma unroll
            for (int bf = 0; bf < 3; bf++)
#pragma unroll
                for (int sub = 0; sub < 2; sub++) {
                    float* c = acc[bf * 2 + sub];
                    int n = ncol + bf * 16 + sub * 8;
                    *(float2*)&ghs[mrow * 100 + n] = make_float2(c[0], c[1]);
                    *(float2*)&ghs[(mrow + 8) * 100 + n] = make_float2(c[2], c[3]);
                }
        }
        __syncthreads();

        // ---- gates + h update (thread = row b_loc, h0..h0+7) ----
        {
            float x0 = Xs[b_loc * 3], x1 = Xs[b_loc * 3 + 1], x2 = Xs[b_loc * 3 + 2];
            const float* gr = &ghs[b_loc * 100];
            __half2 ph[4], pl[4];
            float hf[8];
#pragma unroll
            for (int j = 0; j < 8; j++) {
                int hh = h0 + j;
                float ghr = gr[hh];
                float ghz = gr[32 + hh];
                float ghn = gr[64 + hh];
                const float* wr = &wihs[(0 * 32 + hh) * 3];
                const float* wz = &wihs[(1 * 32 + hh) * 3];
                const float* wn = &wihs[(2 * 32 + hh) * 3];
                float gi_r = fmaf(x2, wr[2], fmaf(x1, wr[1], x0 * wr[0])) + bihs[hh];
                float gi_z = fmaf(x2, wz[2], fmaf(x1, wz[1], x0 * wz[0])) + bihs[32 + hh];
                float gi_n = fmaf(x2, wn[2], fmaf(x1, wn[1], x0 * wn[0])) + bihs[64 + hh];
                float r = sigf(gi_r + ghr + bhhs[hh]);
                float z = sigf(gi_z + ghz + bhhs[32 + hh]);
                float n = tanhf_fast(gi_n + r * (ghn + bhhs[64 + hh]));
                float hn = n + z * (hprev[j] - n);
                hprev[j] = hn;
                hf[j] = hn;
            }
#pragma unroll
            for (int j = 0; j < 4; j++) {
                __half e0 = __float2half_rn(hf[2 * j]);
                __half e1 = __float2half_rn(hf[2 * j + 1]);
                ph[j] = __halves2half2(e0, e1);
                pl[j] = __halves2half2(
                    __float2half_rn(hf[2 * j] - __half2float(e0)),
                    __float2half_rn(hf[2 * j + 1] - __half2float(e1)));
            }
            size_t hxo = (size_t)bglob * HH + hb0 + h0;
            *(uint4*)&g_hx[t & 1][hxo] =
                make_uint4(*(uint32_t*)&ph[0], *(uint32_t*)&ph[1],
                           *(uint32_t*)&ph[2], *(uint32_t*)&ph[3]);
            *(uint4*)&g_hxlo[t & 1][hxo] =
                make_uint4(*(uint32_t*)&pl[0], *(uint32_t*)&pl[1],
                           *(uint32_t*)&pl[2], *(uint32_t*)&pl[3]);
            float* ec = &g_enc[((size_t)bglob * TT + t) * HH + hb0 + h0];
            *(float4*)&ec[0] = make_float4(hf[0], hf[1], hf[2], hf[3]);
            *(float4*)&ec[4] = make_float4(hf[4], hf[5], hf[6], hf[7]);
            if (t == TT - 1) {
                float* hd = &g_h1[(size_t)bglob * HH + hb0 + h0];
                *(float4*)&hd[0] = make_float4(hf[0], hf[1], hf[2], hf[3]);
                *(float4*)&hd[4] = make_float4(hf[4], hf[5], hf[6], hf[7]);
            }
        }

        // ---- per-batch-group barrier (8 arrivals) ----
        __syncthreads();
        if (tid == 0) {
            red_release_add(&g_barcnt[bg], 1u);
            unsigned target = 8u * (unsigned)(t + 1);
            while (ld_acq(&g_barcnt[bg]) < target) { }
        }
        __syncthreads();
    }
}

// ---------------- eproj: C = A @ W^T (64x64 tiles, R5 version) ----------------
__global__ __launch_bounds__(256) void eproj_kernel() {
    const float* __restrict__ A = g_enc;
    const float* __restrict__ W = g_wte;
    float* __restrict__ C = g_eproj;
    const int K = HH, N = HH;
    __shared__ __align__(16) float As[16][64];
    __shared__ __align__(16) float Ws[16][64];
    int tid = threadIdx.x;
    int m0 = blockIdx.x * 64, n0 = blockIdx.y * 64;
    int tx = tid & 15, ty = tid >> 4;
    u64 acc[4][2];
#pragma unroll
    for (int i = 0; i < 4; i++)
#pragma unroll
        for (int j = 0; j < 2; j++) acc[i][j] = 0ull;
    int lr = tid >> 2, lq = tid & 3;
    for (int k0 = 0; k0 < K; k0 += 16) {
        __syncthreads();
        {
            float4 v = *(const float4*)&A[(size_t)(m0 + lr) * K + k0 + lq * 4];
            As[lq * 4 + 0][lr] = v.x; As[lq * 4 + 1][lr] = v.y;
            As[lq * 4 + 2][lr] = v.z; As[lq * 4 + 3][lr] = v.w;
        }
        {
            float4 v = *(const float4*)&W[(size_t)(n0 + lr) * K + k0 + lq * 4];
            Ws[lq * 4 + 0][lr] = v.x; Ws[lq * 4 + 1][lr] = v.y;
            Ws[lq * 4 + 2][lr] = v.z; Ws[lq * 4 + 3][lr] = v.w;
        }
        __syncthreads();
#pragma unroll
        for (int k = 0; k < 16; k++) {
            float4 a4 = *(const float4*)&As[k][ty * 4];
            u64 w0 = *(const u64*)&Ws[k][tx * 4];
            u64 w1 = *(const u64*)&Ws[k][tx * 4 + 2];
            u64 a;
            a = pack2(a4.x, a4.x); fma2(acc[0][0], a, w0); fma2(acc[0][1], a, w1);
            a = pack2(a4.y, a4.y); fma2(acc[1][0], a, w0); fma2(acc[1][1], a, w1);
            a = pack2(a4.z, a4.z); fma2(acc[2][0], a, w0); fma2(acc[2][1], a, w1);
            a = pack2(a4.w, a4.w); fma2(acc[3][0], a, w0); fma2(acc[3][1], a, w1);
        }
    }
#pragma unroll
    for (int i = 0; i < 4; i++) {
        int m = m0 + ty * 4 + i;
#pragma unroll
        for (int j = 0; j < 2; j++) {
            float lo, hi; unpack2(acc[i][j], lo, hi);
            int n = n0 + tx * 4 + j * 2;
            C[(size_t)m * N + n] = lo;
            C[(size_t)m * N + n + 1] = hi;
        }
    }
}

// ---------------- dproj ----------------
__global__ __launch_bounds__(256) void dproj_kernel(const float* __restrict__ bt, int s) {
    const float* A = (s == 0) ? g_h1 : g_hd[s & 1];
    __shared__ __align__(16) float As[32][32];
    __shared__ __align__(16) float Ws[32][32];
    int tid = threadIdx.x;
    int m0 = blockIdx.x * 32, n0 = blockIdx.y * 32;
    int tx = tid & 15, ty = tid >> 4;
    u64 acc[2] = {0ull, 0ull};
    int lr = tid >> 3, lq = tid & 7;
    for (int k0 = 0; k0 < HH; k0 += 32) {
        __syncthreads();
        {
            float4 v = *(const float4*)&A[(size_t)(m0 + lr) * HH + k0 + lq * 4];
            As[lq * 4 + 0][lr] = v.x; As[lq * 4 + 1][lr] = v.y;
            As[lq * 4 + 2][lr] = v.z; As[lq * 4 + 3][lr] = v.w;
        }
        {
            float4 v = *(const float4*)&g_wtd[(size_t)(n0 + lr) * HH + k0 + lq * 4];
            Ws[lq * 4 + 0][lr] = v.x; Ws[lq * 4 + 1][lr] = v.y;
            Ws[lq * 4 + 2][lr] = v.z; Ws[lq * 4 + 3][lr] = v.w;
        }
        __syncthreads();
#pragma unroll
        for (int k = 0; k < 32; k++) {
            float2 a2 = *(const float2*)&As[k][ty * 2];
            u64 w = *(const u64*)&Ws[k][tx * 2];
            fma2(acc[0], pack2(a2.x, a2.x), w);
            fma2(acc[1], pack2(a2.y, a2.y), w);
        }
    }
#pragma unroll
    for (int i = 0; i < 2; i++) {
        float lo, hi; unpack2(acc[i], lo, hi);
        int m = m0 + ty * 2 + i, n = n0 + tx * 2;
        g_dproj[(size_t)m * HH + n] = lo + bt[n];
        g_dproj[(size_t)m * HH + n + 1] = hi + bt[n + 1];
    }
}

// ---------------- decoder temporal attention (R5) ----------------
__global__ __launch_bounds__(256) void tscore_kernel(const float* __restrict__ vt) {
    int b = blockIdx.y;
    int tid = threadIdx.x;
    __shared__ float dps[HH], vts[HH];
    dps[tid] = g_dproj[(size_t)b * HH + tid];
    vts[tid] = vt[tid];
    __syncthreads();
    int w = tid >> 5, lane = tid & 31;
    int t = blockIdx.x * 8 + w;
    const float* row = &g_eproj[((size_t)b * TT + t) * HH];
    float s = 0.0f;
#pragma unroll
    for (int i = 0; i < 8; i++) {
        int h = lane + 32 * i;
        s += tanhf_fast(row[h] + dps[h]) * vts[h];
    }
    s = warp_sum(s);
    if (lane == 0) g_ts[(size_t)b * TT + t] = s;
}

__global__ __launch_bounds__(256) void softmax_t_kernel() {
    int b = blockIdx.x, tid = threadIdx.x;
    __shared__ float sm[256];
    float v = g_ts[(size_t)b * TT + tid];
    sm[tid] = v;
    __syncthreads();
    for (int o = 128; o > 0; o >>= 1) {
        if (tid < o) sm[tid] = fmaxf(sm[tid], sm[tid + o]);
        __syncthreads();
    }
    float m = sm[0];
    __syncthreads();
    float e = ex2f((v - m) * 1.4426950408889634f);
    sm[tid] = e;
    __syncthreads();
    for (int o = 128; o > 0; o >>= 1) {
        if (tid < o) sm[tid] += sm[tid + o];
        __syncthreads();
    }
    g_tw[(size_t)b * TT + tid] = e * frcp(sm[0]);
}

__global__ __launch_bounds__(128) void context_kernel() {
    int b = blockIdx.y, tid = threadIdx.x;
    int h = blockIdx.x * 128 + tid;
    __shared__ float tws[TT];
    tws[tid] = g_tw[(size_t)b * TT + tid];
    tws[tid + 128] = g_tw[(size_t)b * TT + tid + 128];
    __syncthreads();
    const float* base = &g_enc[(size_t)b * TT * HH + h];
    float acc = 0.0f;
#pragma unroll 4
    for (int t = 0; t < TT; t++) acc += tws[t] * base[(size_t)t * HH];
    g_inp[b * INPAD + OUTD + h] = acc;
}

// ---------------- decoder GRU step (R5) ----------------
template <int TGN>
__device__ __forceinline__ void gemm_gate_phase(
        u64 (&acc)[4][4],
        const float* __restrict__ Ain, int astr,
        const float* __restrict__ Wm, int wstr, int Ktot,
        int bm0, int hb0, int tid, int tx, int ty,
        float (&As)[16][64], float (&Ws)[3][16][32]) {
    int lr = tid >> 2, lq = tid & 3;
    for (int k0 = 0; k0 < Ktot; k0 += 16) {
        __syncthreads();
        {
            float4 v = *(const float4*)&Ain[(size_t)(bm0 + lr) * astr + k0 + lq * 4];
            As[lq * 4 + 0][lr] = v.x; As[lq * 4 + 1][lr] = v.y;
            As[lq * 4 + 2][lr] = v.z; As[lq * 4 + 3][lr] = v.w;
        }
        for (int i = tid; i < 384; i += 256) {
            int row = i >> 2, q = i & 3, g = row >> 5, hh = row & 31;
            float4 v = *(const float4*)&Wm[(size_t)(g * HH + hb0 + hh) * wstr + k0 + q * 4];
            Ws[g][q * 4 + 0][hh] = v.x; Ws[g][q * 4 + 1][hh] = v.y;
            Ws[g][q * 4 + 2][hh] = v.z; Ws[g][q * 4 + 3][hh] = v.w;
        }
        __syncthreads();
#pragma unroll
        for (int k = 0; k < 16; k++) {
            float4 a4 = *(const float4*)&As[k][ty * 4];
            u64 w0 = *(const u64*)&Ws[0][k][tx * 2];
            u64 w1 = *(const u64*)&Ws[1][k][tx * 2];
            u64 w2 = *(const u64*)&Ws[2][k][tx * 2];
            u64 a;
            a = pack2(a4.x, a4.x); fma2(acc[0][0], a, w0); fma2(acc[1][0], a, w1); fma2(acc[TGN][0], a, w2);
            a = pack2(a4.y, a4.y); fma2(acc[0][1], a, w0); fma2(acc[1][1], a, w1); fma2(acc[TGN][1], a, w2);
            a = pack2(a4.z, a4.z); fma2(acc[0][2], a, w0); fma2(acc[1][2], a, w1); fma2(acc[TGN][2], a, w2);
            a = pack2(a4.w, a4.w); fma2(acc[0][3], a, w0); fma2(acc[1][3], a, w1); fma2(acc[TGN][3], a, w2);
        }
    }
}

__global__ __launch_bounds__(256) void dec_gru_kernel(
        const float* __restrict__ Whh, const float* __restrict__ bih,
        const float* __restrict__ bhh, int s) {
    const float* hin = (s == 0) ? g_h1 : g_hd[s & 1];
    float* hout = g_hd[(s + 1) & 1];

    __shared__ __align__(16) float As[16][64];
    __shared__ __align__(16) float Ws[3][16][32];
    __shared__ float bihs[3][32], bhhs[3][32];

    int tid = threadIdx.x;
    int bm0 = blockIdx.x * 64, hb0 = blockIdx.y * 32;
    int tx = tid & 15, ty = tid >> 4;
    if (tid < 96) {
        int g = tid >> 5, hh = tid & 31;
        bihs[g][hh] = bih[g * HH + hb0 + hh];
        bhhs[g][hh] = bhh[g * HH + hb0 + hh];
    }

    u64 acc[4][4];
#pragma unroll
    for (int g = 0; g < 4; g++)
#pragma unroll
        for (int i = 0; i < 4; i++) acc[g][i] = 0ull;

    gemm_gate_phase<2>(acc, hin, HH, Whh, HH, HH, bm0, hb0, tid, tx, ty, As, Ws);
    gemm_gate_phase<3>(acc, g_inp, INPAD, g_wihp, INPAD, INPAD, bm0, hb0, tid, tx, ty, As, Ws);

#pragma unroll
    for (int i = 0; i < 4; i++) {
        int b = bm0 + ty * 4 + i;
        float2 hp = *(const float2*)&hin[(size_t)b * HH + hb0 + tx * 2];
        float a0[2], a1[2], a2[2], a3[2];
        unpack2(acc[0][i], a0[0], a0[1]);
        unpack2(acc[1][i], a1[0], a1[1]);
        unpack2(acc[2][i], a2[0], a2[1]);
        unpack2(acc[3][i], a3[0], a3[1]);
#pragma unroll
        for (int j = 0; j < 2; j++) {
            int hl = tx * 2 + j;
            float r = sigf(a0[j] + bihs[0][hl] + bhhs[0][hl]);
            float z = sigf(a1[j] + bihs[1][hl] + bhhs[1][hl]);
            float n = tanhf_fast((a3[j] + bihs[2][hl]) + r * (a2[j] + bhhs[2][hl]));
            float hprev = (j == 0) ? hp.x : hp.y;
            float hn = n + z * (hprev - n);
            hout[(size_t)b * HH + hb0 + hl] = hn;
        }
    }
}

// ---------------- prediction head ----------------
__global__ __launch_bounds__(288) void pred_kernel(
        const float* __restrict__ Wfc, const float* __restrict__ bfc,
        float* __restrict__ out, int s) {
    int b = blockIdx.x, tid = threadIdx.x;
    const float* h = &g_hd[(s + 1) & 1][(size_t)b * HH];
    __shared__ float hs[HH];
    if (tid < HH) hs[tid] = h[tid];
    __syncthreads();
    int w = tid >> 5, lane = tid & 31;
    float sacc = 0.0f;
#pragma unroll
    for (int i = 0; i < 8; i++) {
        int hh = lane + 32 * i;
        sacc += hs[hh] * Wfc[w * HH + hh];
    }
    sacc = warp_sum(sacc);
    if (lane == 0) {
        float p = sacc + bfc[w];
        out[((size_t)b * PL + s) * OUTD + w] = p;
        g_inp[b * INPAD + w] = p;
    }
}

// ---------------- host orchestration ----------------
extern "C" void kernel_launch(void* const* d_in, const int* in_sizes, int n_in,
                              void* d_out, int out_size) {
    const float* x    = (const float*)d_in[0];
    const float* Wa   = (const float*)d_in[1];
    const float* ba   = (const float*)d_in[2];
    const float* va   = (const float*)d_in[3];
    const float* eWih = (const float*)d_in[4];
    const float* eWhh = (const float*)d_in[5];
    const float* ebih = (const float*)d_in[6];
    const float* ebhh = (const float*)d_in[7];
    const float* dWih = (const float*)d_in[8];
    const float* dWhh = (const float*)d_in[9];
    const float* dbih = (const float*)d_in[10];
    const float* dbhh = (const float*)d_in[11];
    const float* Wt   = (const float*)d_in[12];
    const float* bt   = (const float*)d_in[13];
    const float* vt   = (const float*)d_in[14];
    const float* Wfc  = (const float*)d_in[15];
    const float* bfc  = (const float*)d_in[16];
    float* out = (float*)d_out;

    init_a_kernel<<<256, 256>>>(x);
    init_b_kernel<<<256, 256>>>(dWih, Wt);
    agent_attn_kernel<<<(BB * TT) / 8, 256>>>(x, Wa, ba, va);

    cudaFuncSetAttribute(enc_persistent,
                         cudaFuncAttributeMaxDynamicSharedMemorySize, ENC_SMEM);
    enc_persistent<<<128, 256, ENC_SMEM>>>(eWhh, eWih, ebih, ebhh);

    eproj_kernel<<<dim3((BB * TT) / 64, HH / 64), 256>>>();

    for (int s = 0; s < PL; s++) {
        dproj_kernel<<<dim3(BB / 32, HH / 32), 256>>>(bt, s);
        tscore_kernel<<<dim3(TT / 8, BB), 256>>>(vt);
        softmax_t_kernel<<<BB, 256>>>();
        context_kernel<<<dim3(HH / 128, BB), 128>>>();
        dec_gru_kernel<<<dim3(BB / 64, HH / 32), 256>>>(dWhh, dbih, dbhh, s);
        pred_kernel<<<BB, 288>>>(Wfc, bfc, out, s);
    }
}

// round 9
// speedup vs baseline: 1.7843x; 1.7843x over previous
#include <cuda_runtime.h>
#include <cuda_fp16.h>
#include <cstdint>

#define BB 1024
#define TT 256
#define HH 256
#define OUTD 9
#define PL 16
#define INPAD 272   // 9 + 256 = 265, padded to 272

typedef unsigned long long u64;

// ---------------- device scratch ----------------
__device__ __align__(16) float g_reprs[BB * TT * 3];
__device__ __align__(16) float g_enc[(size_t)BB * TT * HH];
__device__ __align__(16) float g_eproj[(size_t)BB * TT * HH];
__device__ __align__(16) __half g_hx[2][BB * HH];     // fp16 h exchange ping-pong
__device__ __align__(16) float g_h1[BB * HH];         // final encoder h (fp32)
__device__ __align__(16) float g_hd[2][BB * HH];
__device__ __align__(16) float g_dproj[BB * HH];
__device__ __align__(16) float g_ts[BB * TT];
__device__ __align__(16) float g_tw[BB * TT];
__device__ __align__(16) float g_inp[BB * INPAD];
__device__ __align__(16) float g_wihp[768 * INPAD];
__device__ __align__(16) float g_wtd[HH * HH];
__device__ __align__(16) float g_wte[HH * HH];
__device__ unsigned g_barcnt[16];

// ---------------- math helpers ----------------
__device__ __forceinline__ float ex2f(float x) {
    float r; asm("ex2.approx.f32 %0, %1;" : "=f"(r) : "f"(x)); return r;
}
__device__ __forceinline__ float frcp(float x) {
    float r; asm("rcp.approx.f32 %0, %1;" : "=f"(r) : "f"(x)); return r;
}
__device__ __forceinline__ float sigf(float x) {
    return frcp(1.0f + ex2f(-1.4426950408889634f * x));
}
__device__ __forceinline__ float tanhf_fast(float x) {
    float ax = fabsf(x);
    float e = ex2f(-2.8853900817779268f * ax);
    float r = (1.0f - e) * frcp(1.0f + e);
    return copysignf(r, x);
}
__device__ __forceinline__ u64 pack2(float lo, float hi) {
    u64 r;
    asm("mov.b64 %0, {%1, %2};" : "=l"(r)
        : "r"(__float_as_uint(lo)), "r"(__float_as_uint(hi)));
    return r;
}
__device__ __forceinline__ void unpack2(u64 v, float& lo, float& hi) {
    unsigned a, b;
    asm("mov.b64 {%0, %1}, %2;" : "=r"(a), "=r"(b) : "l"(v));
    lo = __uint_as_float(a); hi = __uint_as_float(b);
}
__device__ __forceinline__ void fma2(u64& d, u64 a, u64 b) {
    asm("fma.rn.f32x2 %0, %1, %2, %0;" : "+l"(d) : "l"(a), "l"(b));
}
__device__ __forceinline__ float warp_sum(float v) {
#pragma unroll
    for (int o = 16; o > 0; o >>= 1) v += __shfl_xor_sync(0xffffffffu, v, o);
    return v;
}
__device__ __forceinline__ unsigned ld_acq(const unsigned* p) {
    unsigned v;
    asm volatile("ld.acquire.gpu.u32 %0, [%1];" : "=r"(v) : "l"(p));
    return v;
}
__device__ __forceinline__ void red_release_add(unsigned* p, unsigned v) {
    asm volatile("red.release.gpu.global.add.u32 [%0], %1;" :: "l"(p), "r"(v) : "memory");
}
__device__ __forceinline__ uint32_t smem_u32(const void* p) {
    uint32_t a;
    asm("{ .reg .u64 t; cvta.to.shared.u64 t, %1; cvt.u32.u64 %0, t; }"
        : "=r"(a) : "l"(p));
    return a;
}
__device__ __forceinline__ void ldm4(uint32_t* r, uint32_t addr) {
    asm volatile("ldmatrix.sync.aligned.m8n8.x4.shared.b16 {%0,%1,%2,%3}, [%4];"
        : "=r"(r[0]), "=r"(r[1]), "=r"(r[2]), "=r"(r[3]) : "r"(addr));
}
__device__ __forceinline__ void mma16816(float* c,
        uint32_t a0, uint32_t a1, uint32_t a2, uint32_t a3,
        uint32_t b0, uint32_t b1) {
    asm volatile(
        "mma.sync.aligned.m16n8k16.row.col.f32.f16.f16.f32 "
        "{%0,%1,%2,%3}, {%4,%5,%6,%7}, {%8,%9}, {%0,%1,%2,%3};"
        : "+f"(c[0]), "+f"(c[1]), "+f"(c[2]), "+f"(c[3])
        : "r"(a0), "r"(a1), "r"(a2), "r"(a3), "r"(b0), "r"(b1));
}

// ---------------- init ----------------
__global__ void init_a_kernel(const float* __restrict__ x) {
    int idx = blockIdx.x * blockDim.x + threadIdx.x;
    int stride = gridDim.x * blockDim.x;
    if (idx < 16) g_barcnt[idx] = 0u;
    for (int i = idx; i < BB * INPAD; i += stride) {
        int b = i / INPAD, c = i - b * INPAD;
        g_inp[i] = (c < OUTD) ? x[((size_t)b * TT + (TT - 1)) * OUTD + c] : 0.0f;
    }
}
__global__ void init_b_kernel(const float* __restrict__ dWih,
                              const float* __restrict__ Wt) {
    int idx = blockIdx.x * blockDim.x + threadIdx.x;
    int stride = gridDim.x * blockDim.x;
    for (int i = idx; i < 768 * INPAD; i += stride) {
        int row = i / INPAD, c = i - row * INPAD;
        g_wihp[i] = (c < OUTD + HH) ? dWih[row * (OUTD + HH) + c] : 0.0f;
    }
    for (int i = idx; i < HH * HH; i += stride) {
        int g = i >> 8, c = i & 255;
        g_wtd[i] = Wt[g * (2 * HH) + c];
        g_wte[i] = Wt[g * (2 * HH) + HH + c];
    }
}

// ---------------- stage 1: agent attention ----------------
__global__ __launch_bounds__(256) void agent_attn_kernel(
        const float* __restrict__ x, const float* __restrict__ Wa,
        const float* __restrict__ ba, const float* __restrict__ va) {
    __shared__ float Was[HH * 3];
    __shared__ float vas[HH];
    __shared__ float bas[HH];
    int tid = threadIdx.x;
    for (int i = tid; i < HH * 3; i += 256) Was[i] = Wa[i];
    vas[tid] = va[tid];
    bas[tid] = ba[tid];
    __syncthreads();

    int pair = blockIdx.x * 8 + (tid >> 5);
    int lane = tid & 31;
    const float* xp = &x[(size_t)pair * 9];
    float xv[9];
#pragma unroll
    for (int i = 0; i < 9; i++) xv[i] = xp[i];

    float sc[3];
#pragma unroll
    for (int a = 0; a < 3; a++) {
        float s = 0.0f;
        float x0 = xv[a * 3], x1 = xv[a * 3 + 1], x2 = xv[a * 3 + 2];
#pragma unroll
        for (int i = 0; i < 8; i++) {
            int h = lane + 32 * i;
            float e = tanhf_fast(fmaf(x2, Was[h * 3 + 2],
                          fmaf(x1, Was[h * 3 + 1], x0 * Was[h * 3])) + bas[h]);
            s += e * vas[h];
        }
        sc[a] = warp_sum(s);
    }
    float m = fmaxf(sc[0], fmaxf(sc[1], sc[2]));
    float e0 = ex2f((sc[0] - m) * 1.4426950408889634f);
    float e1 = ex2f((sc[1] - m) * 1.4426950408889634f);
    float e2 = ex2f((sc[2] - m) * 1.4426950408889634f);
    float inv = frcp(e0 + e1 + e2);
    float a0 = e0 * inv, a1 = e1 * inv, a2 = e2 * inv;
    if (lane < 3) {
        g_reprs[pair * 3 + lane] =
            a0 * xv[lane] + a1 * xv[3 + lane] + a2 * xv[6 + lane];
    }
}

// ---------------- stage 2: mma.sync persistent encoder (1-term fp16) ----------------
// 128 CTAs = 16 batch-groups (64 rows) x 8 h-groups (32 h x 3 gates).
// gh[64,96] = h[64,256] x Whh_slice[96,256]^T via m16n8k16 HMMA (fp16 in, fp32 acc).
#define ROWB 528                          // padded row bytes (264 halves)
#define AHI_OFF 0
#define BHI_OFF (64 * ROWB)
#define GHS_OFF (BHI_OFF + 96 * ROWB)
#define XS_OFF  (GHS_OFF + 64 * 100 * 4)
#define WIH_OFF (XS_OFF + 192 * 4)
#define BIH_OFF (WIH_OFF + 288 * 4)
#define BHH_OFF (BIH_OFF + 96 * 4)
#define ENC_SMEM (BHH_OFF + 96 * 4)

__global__ __launch_bounds__(256, 1) void enc_persistent(
        const float* __restrict__ Whh, const float* __restrict__ Wih,
        const float* __restrict__ bih, const float* __restrict__ bhh) {
    extern __shared__ __align__(16) char smraw[];
    uint32_t smem_base = smem_u32(smraw);
    float* ghs  = (float*)(smraw + GHS_OFF);      // [64][100]
    float* Xs   = (float*)(smraw + XS_OFF);       // [64][3]
    float* wihs = (float*)(smraw + WIH_OFF);      // [3*32][3]
    float* bihs = (float*)(smraw + BIH_OFF);      // [96]
    float* bhhs = (float*)(smraw + BHH_OFF);      // [96]

    int tid = threadIdx.x;
    int wid = tid >> 5, lane = tid & 31;
    int bid = blockIdx.x;
    int bg  = bid >> 3;                // batch group 0..15
    int bm0 = bg * 64;
    int hb0 = (bid & 7) * 32;

    // ---- zero A tile (t=0 uses h=0; pad stays 0 forever) ----
    for (int i = tid; i < (64 * ROWB) / 16; i += 256)
        ((uint4*)smraw)[i] = make_uint4(0, 0, 0, 0);

    // ---- stage Whh slice fp16 (rows n = g*32+hh, k-contig, padded) ----
    for (int i = tid; i < 96 * 128; i += 256) {
        int n = i >> 7, kp = i & 127;
        int g = n >> 5, hh = n & 31;
        float2 w = *(const float2*)&Whh[(size_t)(g * HH + hb0 + hh) * HH + kp * 2];
        *(__half2*)(smraw + BHI_OFF + n * ROWB + kp * 4) = __floats2half2_rn(w.x, w.y);
    }
    for (int i = tid; i < 288; i += 256) {
        int g = i / 96, r = i % 96, hh = r / 3, f = r % 3;
        wihs[(g * 32 + hh) * 3 + f] = Wih[(size_t)(g * HH + hb0 + hh) * 3 + f];
    }
    if (tid < 96) {
        int g = tid >> 5, hh = tid & 31;
        bihs[g * 32 + hh] = bih[g * HH + hb0 + hh];
        bhhs[g * 32 + hh] = bhh[g * HH + hb0 + hh];
    }
    __syncthreads();

    // warp tile: mw in 0..3 (m = mw*16), nw in 0..1 (n = nw*48)
    int mw = wid >> 1, nw = wid & 1;
    uint32_t a_off = (uint32_t)(((lane & 7) + ((lane >> 3) & 1) * 8) * ROWB
                                + ((lane >> 4) & 1) * 16);
    uint32_t b_off = (uint32_t)(((lane & 7) + ((lane >> 4) & 1) * 8) * ROWB
                                + ((lane >> 3) & 1) * 16);
    uint32_t Ah = smem_base + AHI_OFF + mw * 16 * ROWB + a_off;
    uint32_t Bh = smem_base + BHI_OFF + nw * 48 * ROWB + b_off;

    // epilogue thread mapping: row b_loc, 8 h each
    int b_loc = tid >> 2;
    int h0 = (tid & 3) * 8;
    int bglob = bm0 + b_loc;
    float hprev[8];
#pragma unroll
    for (int j = 0; j < 8; j++) hprev[j] = 0.0f;

    for (int t = 0; t < TT; t++) {
        // ---- stage A = h_{t-1} fp16 into padded tile ----
        if (t > 0) {
            const __half* hsrc = g_hx[(t + 1) & 1];
            for (int i = tid; i < 2048; i += 256) {
                int r = i >> 5, kc = i & 31;    // row, 8-half chunk
                uint4 v = __ldcg((const uint4*)&hsrc[(size_t)(bm0 + r) * HH + kc * 8]);
                *(uint4*)(smraw + AHI_OFF + r * ROWB + kc * 16) = v;
            }
        }
        if (tid < 192) {
            int b = tid / 3, f = tid % 3;
            Xs[b * 3 + f] = g_reprs[((size_t)(bm0 + b) * TT + t) * 3 + f];
        }
        __syncthreads();

        // ---- MMA mainloop: 16 k-chunks, 6 MMAs each ----
        float acc[6][4];
#pragma unroll
        for (int f = 0; f < 6; f++)
#pragma unroll
            for (int q = 0; q < 4; q++) acc[f][q] = 0.0f;

#pragma unroll 4
        for (int ks = 0; ks < 16; ks++) {
            uint32_t koff = ks * 32;
            uint32_t ah[4], bh[3][4];
            ldm4(ah, Ah + koff);
#pragma unroll
            for (int f = 0; f < 3; f++) ldm4(bh[f], Bh + f * 16 * ROWB + koff);
#pragma unroll
            for (int f = 0; f < 3; f++) {
                mma16816(acc[2 * f],     ah[0], ah[1], ah[2], ah[3], bh[f][0], bh[f][1]);
                mma16816(acc[2 * f + 1], ah[0], ah[1], ah[2], ah[3], bh[f][2], bh[f][3]);
            }
        }

        // ---- scatter gh fragments to smem ----
        {
            int mrow = mw * 16 + (lane >> 2);
            int ncol = nw * 48 + 2 * (lane & 3);
#pragma unroll
            for (int bf = 0; bf < 3; bf++)
#pragma unroll
                for (int sub = 0; sub < 2; sub++) {
                    float* c = acc[bf * 2 + sub];
                    int n = ncol + bf * 16 + sub * 8;
                    *(float2*)&ghs[mrow * 100 + n] = make_float2(c[0], c[1]);
                    *(float2*)&ghs[(mrow + 8) * 100 + n] = make_float2(c[2], c[3]);
                }
        }
        __syncthreads();

        // ---- gates + h update (thread = row b_loc, h0..h0+7) ----
        float hf[8];
        {
            float x0 = Xs[b_loc * 3], x1 = Xs[b_loc * 3 + 1], x2 = Xs[b_loc * 3 + 2];
            const float* gr = &ghs[b_loc * 100];
#pragma unroll
            for (int j = 0; j < 8; j++) {
                int hh = h0 + j;
                float ghr = gr[hh];
                float ghz = gr[32 + hh];
                float ghn = gr[64 + hh];
                const float* wr = &wihs[(0 * 32 + hh) * 3];
                const float* wz = &wihs[(1 * 32 + hh) * 3];
                const float* wn = &wihs[(2 * 32 + hh) * 3];
                float gi_r = fmaf(x2, wr[2], fmaf(x1, wr[1], x0 * wr[0])) + bihs[hh];
                float gi_z = fmaf(x2, wz[2], fmaf(x1, wz[1], x0 * wz[0])) + bihs[32 + hh];
                float gi_n = fmaf(x2, wn[2], fmaf(x1, wn[1], x0 * wn[0])) + bihs[64 + hh];
                float r = sigf(gi_r + ghr + bhhs[hh]);
                float z = sigf(gi_z + ghz + bhhs[32 + hh]);
                float n = tanhf_fast(gi_n + r * (ghn + bhhs[64 + hh]));
                float hn = n + z * (hprev[j] - n);
                hprev[j] = hn;
                hf[j] = hn;
            }
            __half2 ph[4];
#pragma unroll
            for (int j = 0; j < 4; j++)
                ph[j] = __floats2half2_rn(hf[2 * j], hf[2 * j + 1]);
            size_t hxo = (size_t)bglob * HH + hb0 + h0;
            *(uint4*)&g_hx[t & 1][hxo] =
                make_uint4(*(uint32_t*)&ph[0], *(uint32_t*)&ph[1],
                           *(uint32_t*)&ph[2], *(uint32_t*)&ph[3]);
        }

        // ---- barrier arrive, then non-critical stores overlap the spin ----
        __syncthreads();
        if (tid == 0) red_release_add(&g_barcnt[bg], 1u);
        {
            float* ec = &g_enc[((size_t)bglob * TT + t) * HH + hb0 + h0];
            *(float4*)&ec[0] = make_float4(hf[0], hf[1], hf[2], hf[3]);
            *(float4*)&ec[4] = make_float4(hf[4], hf[5], hf[6], hf[7]);
            if (t == TT - 1) {
                float* hd = &g_h1[(size_t)bglob * HH + hb0 + h0];
                *(float4*)&hd[0] = make_float4(hf[0], hf[1], hf[2], hf[3]);
                *(float4*)&hd[4] = make_float4(hf[4], hf[5], hf[6], hf[7]);
            }
        }
        if (tid == 0) {
            unsigned target = 8u * (unsigned)(t + 1);
            while (ld_acq(&g_barcnt[bg]) < target) { }
        }
        __syncthreads();
    }
}

// ---------------- eproj: C = A @ W^T (64x64 tiles) ----------------
__global__ __launch_bounds__(256) void eproj_kernel() {
    const float* __restrict__ A = g_enc;
    const float* __restrict__ W = g_wte;
    float* __restrict__ C = g_eproj;
    const int K = HH, N = HH;
    __shared__ __align__(16) float As[16][64];
    __shared__ __align__(16) float Ws[16][64];
    int tid = threadIdx.x;
    int m0 = blockIdx.x * 64, n0 = blockIdx.y * 64;
    int tx = tid & 15, ty = tid >> 4;
    u64 acc[4][2];
#pragma unroll
    for (int i = 0; i < 4; i++)
#pragma unroll
        for (int j = 0; j < 2; j++) acc[i][j] = 0ull;
    int lr = tid >> 2, lq = tid & 3;
    for (int k0 = 0; k0 < K; k0 += 16) {
        __syncthreads();
        {
            float4 v = *(const float4*)&A[(size_t)(m0 + lr) * K + k0 + lq * 4];
            As[lq * 4 + 0][lr] = v.x; As[lq * 4 + 1][lr] = v.y;
            As[lq * 4 + 2][lr] = v.z; As[lq * 4 + 3][lr] = v.w;
        }
        {
            float4 v = *(const float4*)&W[(size_t)(n0 + lr) * K + k0 + lq * 4];
            Ws[lq * 4 + 0][lr] = v.x; Ws[lq * 4 + 1][lr] = v.y;
            Ws[lq * 4 + 2][lr] = v.z; Ws[lq * 4 + 3][lr] = v.w;
        }
        __syncthreads();
#pragma unroll
        for (int k = 0; k < 16; k++) {
            float4 a4 = *(const float4*)&As[k][ty * 4];
            u64 w0 = *(const u64*)&Ws[k][tx * 4];
            u64 w1 = *(const u64*)&Ws[k][tx * 4 + 2];
            u64 a;
            a = pack2(a4.x, a4.x); fma2(acc[0][0], a, w0); fma2(acc[0][1], a, w1);
            a = pack2(a4.y, a4.y); fma2(acc[1][0], a, w0); fma2(acc[1][1], a, w1);
            a = pack2(a4.z, a4.z); fma2(acc[2][0], a, w0); fma2(acc[2][1], a, w1);
            a = pack2(a4.w, a4.w); fma2(acc[3][0], a, w0); fma2(acc[3][1], a, w1);
        }
    }
#pragma unroll
    for (int i = 0; i < 4; i++) {
        int m = m0 + ty * 4 + i;
#pragma unroll
        for (int j = 0; j < 2; j++) {
            float lo, hi; unpack2(acc[i][j], lo, hi);
            int n = n0 + tx * 4 + j * 2;
            C[(size_t)m * N + n] = lo;
            C[(size_t)m * N + n + 1] = hi;
        }
    }
}

// ---------------- dproj ----------------
__global__ __launch_bounds__(256) void dproj_kernel(const float* __restrict__ bt, int s) {
    const float* A = (s == 0) ? g_h1 : g_hd[s & 1];
    __shared__ __align__(16) float As[32][32];
    __shared__ __align__(16) float Ws[32][32];
    int tid = threadIdx.x;
    int m0 = blockIdx.x * 32, n0 = blockIdx.y * 32;
    int tx = tid & 15, ty = tid >> 4;
    u64 acc[2] = {0ull, 0ull};
    int lr = tid >> 3, lq = tid & 7;
    for (int k0 = 0; k0 < HH; k0 += 32) {
        __syncthreads();
        {
            float4 v = *(const float4*)&A[(size_t)(m0 + lr) * HH + k0 + lq * 4];
            As[lq * 4 + 0][lr] = v.x; As[lq * 4 + 1][lr] = v.y;
            As[lq * 4 + 2][lr] = v.z; As[lq * 4 + 3][lr] = v.w;
        }
        {
            float4 v = *(const float4*)&g_wtd[(size_t)(n0 + lr) * HH + k0 + lq * 4];
            Ws[lq * 4 + 0][lr] = v.x; Ws[lq * 4 + 1][lr] = v.y;
            Ws[lq * 4 + 2][lr] = v.z; Ws[lq * 4 + 3][lr] = v.w;
        }
        __syncthreads();
#pragma unroll
        for (int k = 0; k < 32; k++) {
            float2 a2 = *(const float2*)&As[k][ty * 2];
            u64 w = *(const u64*)&Ws[k][tx * 2];
            fma2(acc[0], pack2(a2.x, a2.x), w);
            fma2(acc[1], pack2(a2.y, a2.y), w);
        }
    }
#pragma unroll
    for (int i = 0; i < 2; i++) {
        float lo, hi; unpack2(acc[i], lo, hi);
        int m = m0 + ty * 2 + i, n = n0 + tx * 2;
        g_dproj[(size_t)m * HH + n] = lo + bt[n];
        g_dproj[(size_t)m * HH + n + 1] = hi + bt[n + 1];
    }
}

// ---------------- decoder temporal attention ----------------
__global__ __launch_bounds__(256) void tscore_kernel(const float* __restrict__ vt) {
    int b = blockIdx.y;
    int tid = threadIdx.x;
    __shared__ float dps[HH], vts[HH];
    dps[tid] = g_dproj[(size_t)b * HH + tid];
    vts[tid] = vt[tid];
    __syncthreads();
    int w = tid >> 5, lane = tid & 31;
    int t = blockIdx.x * 8 + w;
    const float* row = &g_eproj[((size_t)b * TT + t) * HH];
    float s = 0.0f;
#pragma unroll
    for (int i = 0; i < 8; i++) {
        int h = lane + 32 * i;
        s += tanhf_fast(row[h] + dps[h]) * vts[h];
    }
    s = warp_sum(s);
    if (lane == 0) g_ts[(size_t)b * TT + t] = s;
}

__global__ __launch_bounds__(256) void softmax_t_kernel() {
    int b = blockIdx.x, tid = threadIdx.x;
    __shared__ float sm[256];
    float v = g_ts[(size_t)b * TT + tid];
    sm[tid] = v;
    __syncthreads();
    for (int o = 128; o > 0; o >>= 1) {
        if (tid < o) sm[tid] = fmaxf(sm[tid], sm[tid + o]);
        __syncthreads();
    }
    float m = sm[0];
    __syncthreads();
    float e = ex2f((v - m) * 1.4426950408889634f);
    sm[tid] = e;
    __syncthreads();
    for (int o = 128; o > 0; o >>= 1) {
        if (tid < o) sm[tid] += sm[tid + o];
        __syncthreads();
    }
    g_tw[(size_t)b * TT + tid] = e * frcp(sm[0]);
}

__global__ __launch_bounds__(128) void context_kernel() {
    int b = blockIdx.y, tid = threadIdx.x;
    int h = blockIdx.x * 128 + tid;
    __shared__ float tws[TT];
    tws[tid] = g_tw[(size_t)b * TT + tid];
    tws[tid + 128] = g_tw[(size_t)b * TT + tid + 128];
    __syncthreads();
    const float* base = &g_enc[(size_t)b * TT * HH + h];
    float acc = 0.0f;
#pragma unroll 4
    for (int t = 0; t < TT; t++) acc += tws[t] * base[(size_t)t * HH];
    g_inp[b * INPAD + OUTD + h] = acc;
}

// ---------------- decoder GRU step ----------------
template <int TGN>
__device__ __forceinline__ void gemm_gate_phase(
        u64 (&acc)[4][4],
        const float* __restrict__ Ain, int astr,
        const float* __restrict__ Wm, int wstr, int Ktot,
        int bm0, int hb0, int tid, int tx, int ty,
        float (&As)[16][64], float (&Ws)[3][16][32]) {
    int lr = tid >> 2, lq = tid & 3;
    for (int k0 = 0; k0 < Ktot; k0 += 16) {
        __syncthreads();
        {
            float4 v = *(const float4*)&Ain[(size_t)(bm0 + lr) * astr + k0 + lq * 4];
            As[lq * 4 + 0][lr] = v.x; As[lq * 4 + 1][lr] = v.y;
            As[lq * 4 + 2][lr] = v.z; As[lq * 4 + 3][lr] = v.w;
        }
        for (int i = tid; i < 384; i += 256) {
            int row = i >> 2, q = i & 3, g = row >> 5, hh = row & 31;
            float4 v = *(const float4*)&Wm[(size_t)(g * HH + hb0 + hh) * wstr + k0 + q * 4];
            Ws[g][q * 4 + 0][hh] = v.x; Ws[g][q * 4 + 1][hh] = v.y;
            Ws[g][q * 4 + 2][hh] = v.z; Ws[g][q * 4 + 3][hh] = v.w;
        }
        __syncthreads();
#pragma unroll
        for (int k = 0; k < 16; k++) {
            float4 a4 = *(const float4*)&As[k][ty * 4];
            u64 w0 = *(const u64*)&Ws[0][k][tx * 2];
            u64 w1 = *(const u64*)&Ws[1][k][tx * 2];
            u64 w2 = *(const u64*)&Ws[2][k][tx * 2];
            u64 a;
            a = pack2(a4.x, a4.x); fma2(acc[0][0], a, w0); fma2(acc[1][0], a, w1); fma2(acc[TGN][0], a, w2);
            a = pack2(a4.y, a4.y); fma2(acc[0][1], a, w0); fma2(acc[1][1], a, w1); fma2(acc[TGN][1], a, w2);
            a = pack2(a4.z, a4.z); fma2(acc[0][2], a, w0); fma2(acc[1][2], a, w1); fma2(acc[TGN][2], a, w2);
            a = pack2(a4.w, a4.w); fma2(acc[0][3], a, w0); fma2(acc[1][3], a, w1); fma2(acc[TGN][3], a, w2);
        }
    }
}

__global__ __launch_bounds__(256) void dec_gru_kernel(
        const float* __restrict__ Whh, const float* __restrict__ bih,
        const float* __restrict__ bhh, int s) {
    const float* hin = (s == 0) ? g_h1 : g_hd[s & 1];
    float* hout = g_hd[(s + 1) & 1];

    __shared__ __align__(16) float As[16][64];
    __shared__ __align__(16) float Ws[3][16][32];
    __shared__ float bihs[3][32], bhhs[3][32];

    int tid = threadIdx.x;
    int bm0 = blockIdx.x * 64, hb0 = blockIdx.y * 32;
    int tx = tid & 15, ty = tid >> 4;
    if (tid < 96) {
        int g = tid >> 5, hh = tid & 31;
        bihs[g][hh] = bih[g * HH + hb0 + hh];
        bhhs[g][hh] = bhh[g * HH + hb0 + hh];
    }

    u64 acc[4][4];
#pragma unroll
    for (int g = 0; g < 4; g++)
#pragma unroll
        for (int i = 0; i < 4; i++) acc[g][i] = 0ull;

    gemm_gate_phase<2>(acc, hin, HH, Whh, HH, HH, bm0, hb0, tid, tx, ty, As, Ws);
    gemm_gate_phase<3>(acc, g_inp, INPAD, g_wihp, INPAD, INPAD, bm0, hb0, tid, tx, ty, As, Ws);

#pragma unroll
    for (int i = 0; i < 4; i++) {
        int b = bm0 + ty * 4 + i;
        float2 hp = *(const float2*)&hin[(size_t)b * HH + hb0 + tx * 2];
        float a0[2], a1[2], a2[2], a3[2];
        unpack2(acc[0][i], a0[0], a0[1]);
        unpack2(acc[1][i], a1[0], a1[1]);
        unpack2(acc[2][i], a2[0], a2[1]);
        unpack2(acc[3][i], a3[0], a3[1]);
#pragma unroll
        for (int j = 0; j < 2; j++) {
            int hl = tx * 2 + j;
            float r = sigf(a0[j] + bihs[0][hl] + bhhs[0][hl]);
            float z = sigf(a1[j] + bihs[1][hl] + bhhs[1][hl]);
            float n = tanhf_fast((a3[j] + bihs[2][hl]) + r * (a2[j] + bhhs[2][hl]));
            float hprev = (j == 0) ? hp.x : hp.y;
            float hn = n + z * (hprev - n);
            hout[(size_t)b * HH + hb0 + hl] = hn;
        }
    }
}

// ---------------- prediction head ----------------
__global__ __launch_bounds__(288) void pred_kernel(
        const float* __restrict__ Wfc, const float* __restrict__ bfc,
        float* __restrict__ out, int s) {
    int b = blockIdx.x, tid = threadIdx.x;
    const float* h = &g_hd[(s + 1) & 1][(size_t)b * HH];
    __shared__ float hs[HH];
    if (tid < HH) hs[tid] = h[tid];
    __syncthreads();
    int w = tid >> 5, lane = tid & 31;
    float sacc = 0.0f;
#pragma unroll
    for (int i = 0; i < 8; i++) {
        int hh = lane + 32 * i;
        sacc += hs[hh] * Wfc[w * HH + hh];
    }
    sacc = warp_sum(sacc);
    if (lane == 0) {
        float p = sacc + bfc[w];
        out[((size_t)b * PL + s) * OUTD + w] = p;
        g_inp[b * INPAD + w] = p;
    }
}

// ---------------- host orchestration ----------------
extern "C" void kernel_launch(void* const* d_in, const int* in_sizes, int n_in,
                              void* d_out, int out_size) {
    const float* x    = (const float*)d_in[0];
    const float* Wa   = (const float*)d_in[1];
    const float* ba   = (const float*)d_in[2];
    const float* va   = (const float*)d_in[3];
    const float* eWih = (const float*)d_in[4];
    const float* eWhh = (const float*)d_in[5];
    const float* ebih = (const float*)d_in[6];
    const float* ebhh = (const float*)d_in[7];
    const float* dWih = (const float*)d_in[8];
    const float* dWhh = (const float*)d_in[9];
    const float* dbih = (const float*)d_in[10];
    const float* dbhh = (const float*)d_in[11];
    const float* Wt   = (const float*)d_in[12];
    const float* bt   = (const float*)d_in[13];
    const float* vt   = (const float*)d_in[14];
    const float* Wfc  = (const float*)d_in[15];
    const float* bfc  = (const float*)d_in[16];
    float* out = (float*)d_out;

    init_a_kernel<<<256, 256>>>(x);
    init_b_kernel<<<256, 256>>>(dWih, Wt);
    agent_attn_kernel<<<(BB * TT) / 8, 256>>>(x, Wa, ba, va);

    cudaFuncSetAttribute(enc_persistent,
                         cudaFuncAttributeMaxDynamicSharedMemorySize, ENC_SMEM);
    enc_persistent<<<128, 256, ENC_SMEM>>>(eWhh, eWih, ebih, ebhh);

    eproj_kernel<<<dim3((BB * TT) / 64, HH / 64), 256>>>();

    for (int s = 0; s < PL; s++) {
        dproj_kernel<<<dim3(BB / 32, HH / 32), 256>>>(bt, s);
        tscore_kernel<<<dim3(TT / 8, BB), 256>>>(vt);
        softmax_t_kernel<<<BB, 256>>>();
        context_kernel<<<dim3(HH / 128, BB), 128>>>();
        dec_gru_kernel<<<dim3(BB / 64, HH / 32), 256>>>(dWhh, dbih, dbhh, s);
        pred_kernel<<<BB, 288>>>(Wfc, bfc, out, s);
    }
}

// round 10
// speedup vs baseline: 1.7884x; 1.0023x over previous
#include <cuda_runtime.h>
#include <cuda_fp16.h>
#include <cstdint>

#define BB 1024
#define TT 256
#define HH 256
#define OUTD 9
#define PL 16
#define INPAD 272   // 9 + 256 = 265, padded to 272

typedef unsigned long long u64;

// ---------------- device scratch ----------------
__device__ __align__(16) float g_reprs[BB * TT * 3];
__device__ __align__(16) __half g_enc16[(size_t)BB * TT * HH];
__device__ __align__(16) __half g_eproj16[(size_t)BB * TT * HH];
__device__ __align__(16) __half g_hx[2][BB * HH];     // fp16 h exchange ping-pong
__device__ __align__(16) float g_h1[BB * HH];         // final encoder h (fp32)
__device__ __align__(16) float g_hd[2][BB * HH];
__device__ __align__(16) float g_dproj[BB * HH];
__device__ __align__(16) float g_ts[BB * TT];
__device__ __align__(16) float g_tw[BB * TT];
__device__ __align__(16) float g_inp[BB * INPAD];
__device__ __align__(16) float g_wihp[768 * INPAD];
__device__ __align__(16) float g_wtd[HH * HH];
__device__ __align__(16) float g_wte[HH * HH];
__device__ unsigned g_barcnt[16];

// ---------------- math helpers ----------------
__device__ __forceinline__ float ex2f(float x) {
    float r; asm("ex2.approx.f32 %0, %1;" : "=f"(r) : "f"(x)); return r;
}
__device__ __forceinline__ float frcp(float x) {
    float r; asm("rcp.approx.f32 %0, %1;" : "=f"(r) : "f"(x)); return r;
}
__device__ __forceinline__ float sigf(float x) {
    return frcp(1.0f + ex2f(-1.4426950408889634f * x));
}
__device__ __forceinline__ float tanhf_fast(float x) {
    float ax = fabsf(x);
    float e = ex2f(-2.8853900817779268f * ax);
    float r = (1.0f - e) * frcp(1.0f + e);
    return copysignf(r, x);
}
__device__ __forceinline__ float tanh_apx(float x) {
    float r; asm("tanh.approx.f32 %0, %1;" : "=f"(r) : "f"(x)); return r;
}
__device__ __forceinline__ u64 pack2(float lo, float hi) {
    u64 r;
    asm("mov.b64 %0, {%1, %2};" : "=l"(r)
        : "r"(__float_as_uint(lo)), "r"(__float_as_uint(hi)));
    return r;
}
__device__ __forceinline__ void unpack2(u64 v, float& lo, float& hi) {
    unsigned a, b;
    asm("mov.b64 {%0, %1}, %2;" : "=r"(a), "=r"(b) : "l"(v));
    lo = __uint_as_float(a); hi = __uint_as_float(b);
}
__device__ __forceinline__ void fma2(u64& d, u64 a, u64 b) {
    asm("fma.rn.f32x2 %0, %1, %2, %0;" : "+l"(d) : "l"(a), "l"(b));
}
__device__ __forceinline__ float warp_sum(float v) {
#pragma unroll
    for (int o = 16; o > 0; o >>= 1) v += __shfl_xor_sync(0xffffffffu, v, o);
    return v;
}
__device__ __forceinline__ unsigned ld_acq(const unsigned* p) {
    unsigned v;
    asm volatile("ld.acquire.gpu.u32 %0, [%1];" : "=r"(v) : "l"(p));
    return v;
}
__device__ __forceinline__ void red_release_add(unsigned* p, unsigned v) {
    asm volatile("red.release.gpu.global.add.u32 [%0], %1;" :: "l"(p), "r"(v) : "memory");
}
__device__ __forceinline__ uint32_t smem_u32(const void* p) {
    uint32_t a;
    asm("{ .reg .u64 t; cvta.to.shared.u64 t, %1; cvt.u32.u64 %0, t; }"
        : "=r"(a) : "l"(p));
    return a;
}
__device__ __forceinline__ void ldm4(uint32_t* r, uint32_t addr) {
    asm volatile("ldmatrix.sync.aligned.m8n8.x4.shared.b16 {%0,%1,%2,%3}, [%4];"
        : "=r"(r[0]), "=r"(r[1]), "=r"(r[2]), "=r"(r[3]) : "r"(addr));
}
__device__ __forceinline__ void mma16816(float* c,
        uint32_t a0, uint32_t a1, uint32_t a2, uint32_t a3,
        uint32_t b0, uint32_t b1) {
    asm volatile(
        "mma.sync.aligned.m16n8k16.row.col.f32.f16.f16.f32 "
        "{%0,%1,%2,%3}, {%4,%5,%6,%7}, {%8,%9}, {%0,%1,%2,%3};"
        : "+f"(c[0]), "+f"(c[1]), "+f"(c[2]), "+f"(c[3])
        : "r"(a0), "r"(a1), "r"(a2), "r"(a3), "r"(b0), "r"(b1));
}

// ---------------- init ----------------
__global__ void init_a_kernel(const float* __restrict__ x) {
    int idx = blockIdx.x * blockDim.x + threadIdx.x;
    int stride = gridDim.x * blockDim.x;
    if (idx < 16) g_barcnt[idx] = 0u;
    for (int i = idx; i < BB * INPAD; i += stride) {
        int b = i / INPAD, c = i - b * INPAD;
        g_inp[i] = (c < OUTD) ? x[((size_t)b * TT + (TT - 1)) * OUTD + c] : 0.0f;
    }
}
__global__ void init_b_kernel(const float* __restrict__ dWih,
                              const float* __restrict__ Wt) {
    int idx = blockIdx.x * blockDim.x + threadIdx.x;
    int stride = gridDim.x * blockDim.x;
    for (int i = idx; i < 768 * INPAD; i += stride) {
        int row = i / INPAD, c = i - row * INPAD;
        g_wihp[i] = (c < OUTD + HH) ? dWih[row * (OUTD + HH) + c] : 0.0f;
    }
    for (int i = idx; i < HH * HH; i += stride) {
        int g = i >> 8, c = i & 255;
        g_wtd[i] = Wt[g * (2 * HH) + c];
        g_wte[i] = Wt[g * (2 * HH) + HH + c];
    }
}

// ---------------- stage 1: agent attention ----------------
__global__ __launch_bounds__(256) void agent_attn_kernel(
        const float* __restrict__ x, const float* __restrict__ Wa,
        const float* __restrict__ ba, const float* __restrict__ va) {
    __shared__ float Was[HH * 3];
    __shared__ float vas[HH];
    __shared__ float bas[HH];
    int tid = threadIdx.x;
    for (int i = tid; i < HH * 3; i += 256) Was[i] = Wa[i];
    vas[tid] = va[tid];
    bas[tid] = ba[tid];
    __syncthreads();

    int pair = blockIdx.x * 8 + (tid >> 5);
    int lane = tid & 31;
    const float* xp = &x[(size_t)pair * 9];
    float xv[9];
#pragma unroll
    for (int i = 0; i < 9; i++) xv[i] = xp[i];

    float sc[3];
#pragma unroll
    for (int a = 0; a < 3; a++) {
        float s = 0.0f;
        float x0 = xv[a * 3], x1 = xv[a * 3 + 1], x2 = xv[a * 3 + 2];
#pragma unroll
        for (int i = 0; i < 8; i++) {
            int h = lane + 32 * i;
            float e = tanhf_fast(fmaf(x2, Was[h * 3 + 2],
                          fmaf(x1, Was[h * 3 + 1], x0 * Was[h * 3])) + bas[h]);
            s += e * vas[h];
        }
        sc[a] = warp_sum(s);
    }
    float m = fmaxf(sc[0], fmaxf(sc[1], sc[2]));
    float e0 = ex2f((sc[0] - m) * 1.4426950408889634f);
    float e1 = ex2f((sc[1] - m) * 1.4426950408889634f);
    float e2 = ex2f((sc[2] - m) * 1.4426950408889634f);
    float inv = frcp(e0 + e1 + e2);
    float a0 = e0 * inv, a1 = e1 * inv, a2 = e2 * inv;
    if (lane < 3) {
        g_reprs[pair * 3 + lane] =
            a0 * xv[lane] + a1 * xv[3 + lane] + a2 * xv[6 + lane];
    }
}

// ---------------- stage 2: mma.sync persistent encoder (1-term fp16) ----------------
#define ROWB 528                          // padded row bytes (264 halves)
#define AHI_OFF 0
#define BHI_OFF (64 * ROWB)
#define GHS_OFF (BHI_OFF + 96 * ROWB)
#define XS_OFF  (GHS_OFF + 64 * 100 * 4)
#define WIH_OFF (XS_OFF + 192 * 4)
#define BIH_OFF (WIH_OFF + 288 * 4)
#define BHH_OFF (BIH_OFF + 96 * 4)
#define ENC_SMEM (BHH_OFF + 96 * 4)

__global__ __launch_bounds__(256, 1) void enc_persistent(
        const float* __restrict__ Whh, const float* __restrict__ Wih,
        const float* __restrict__ bih, const float* __restrict__ bhh) {
    extern __shared__ __align__(16) char smraw[];
    uint32_t smem_base = smem_u32(smraw);
    float* ghs  = (float*)(smraw + GHS_OFF);      // [64][100]
    float* Xs   = (float*)(smraw + XS_OFF);       // [64][3]
    float* wihs = (float*)(smraw + WIH_OFF);      // [3*32][3]
    float* bihs = (float*)(smraw + BIH_OFF);      // [96]
    float* bhhs = (float*)(smraw + BHH_OFF);      // [96]

    int tid = threadIdx.x;
    int wid = tid >> 5, lane = tid & 31;
    int bid = blockIdx.x;
    int bg  = bid >> 3;                // batch group 0..15
    int bm0 = bg * 64;
    int hb0 = (bid & 7) * 32;

    // ---- zero A tile (t=0 uses h=0; pad stays 0 forever) ----
    for (int i = tid; i < (64 * ROWB) / 16; i += 256)
        ((uint4*)smraw)[i] = make_uint4(0, 0, 0, 0);

    // ---- stage Whh slice fp16 (rows n = g*32+hh, k-contig, padded) ----
    for (int i = tid; i < 96 * 128; i += 256) {
        int n = i >> 7, kp = i & 127;
        int g = n >> 5, hh = n & 31;
        float2 w = *(const float2*)&Whh[(size_t)(g * HH + hb0 + hh) * HH + kp * 2];
        *(__half2*)(smraw + BHI_OFF + n * ROWB + kp * 4) = __floats2half2_rn(w.x, w.y);
    }
    for (int i = tid; i < 288; i += 256) {
        int g = i / 96, r = i % 96, hh = r / 3, f = r % 3;
        wihs[(g * 32 + hh) * 3 + f] = Wih[(size_t)(g * HH + hb0 + hh) * 3 + f];
    }
    if (tid < 96) {
        int g = tid >> 5, hh = tid & 31;
        bihs[g * 32 + hh] = bih[g * HH + hb0 + hh];
        bhhs[g * 32 + hh] = bhh[g * HH + hb0 + hh];
    }
    __syncthreads();

    int mw = wid >> 1, nw = wid & 1;
    uint32_t a_off = (uint32_t)(((lane & 7) + ((lane >> 3) & 1) * 8) * ROWB
                                + ((lane >> 4) & 1) * 16);
    uint32_t b_off = (uint32_t)(((lane & 7) + ((lane >> 4) & 1) * 8) * ROWB
                                + ((lane >> 3) & 1) * 16);
    uint32_t Ah = smem_base + AHI_OFF + mw * 16 * ROWB + a_off;
    uint32_t Bh = smem_base + BHI_OFF + nw * 48 * ROWB + b_off;

    int b_loc = tid >> 2;
    int h0 = (tid & 3) * 8;
    int bglob = bm0 + b_loc;
    float hprev[8];
#pragma unroll
    for (int j = 0; j < 8; j++) hprev[j] = 0.0f;

    for (int t = 0; t < TT; t++) {
        // ---- stage A = h_{t-1} fp16 into padded tile ----
        if (t > 0) {
            const __half* hsrc = g_hx[(t + 1) & 1];
            for (int i = tid; i < 2048; i += 256) {
                int r = i >> 5, kc = i & 31;
                uint4 v = __ldcg((const uint4*)&hsrc[(size_t)(bm0 + r) * HH + kc * 8]);
                *(uint4*)(smraw + AHI_OFF + r * ROWB + kc * 16) = v;
            }
        }
        if (tid < 192) {
            int b = tid / 3, f = tid % 3;
            Xs[b * 3 + f] = g_reprs[((size_t)(bm0 + b) * TT + t) * 3 + f];
        }
        __syncthreads();

        // ---- MMA mainloop ----
        float acc[6][4];
#pragma unroll
        for (int f = 0; f < 6; f++)
#pragma unroll
            for (int q = 0; q < 4; q++) acc[f][q] = 0.0f;

#pragma unroll 4
        for (int ks = 0; ks < 16; ks++) {
            uint32_t koff = ks * 32;
            uint32_t ah[4], bh[3][4];
            ldm4(ah, Ah + koff);
#pragma unroll
            for (int f = 0; f < 3; f++) ldm4(bh[f], Bh + f * 16 * ROWB + koff);
#pragma unroll
            for (int f = 0; f < 3; f++) {
                mma16816(acc[2 * f],     ah[0], ah[1], ah[2], ah[3], bh[f][0], bh[f][1]);
                mma16816(acc[2 * f + 1], ah[0], ah[1], ah[2], ah[3], bh[f][2], bh[f][3]);
            }
        }

        // ---- scatter gh fragments to smem ----
        {
            int mrow = mw * 16 + (lane >> 2);
            int ncol = nw * 48 + 2 * (lane & 3);
#pragma unroll
            for (int bf = 0; bf < 3; bf++)
#pragma unroll
                for (int sub = 0; sub < 2; sub++) {
                    float* c = acc[bf * 2 + sub];
                    int n = ncol + bf * 16 + sub * 8;
                    *(float2*)&ghs[mrow * 100 + n] = make_float2(c[0], c[1]);
                    *(float2*)&ghs[(mrow + 8) * 100 + n] = make_float2(c[2], c[3]);
                }
        }
        __syncthreads();

        // ---- gates + h update ----
        float hf[8];
        uint4 phq;
        {
            float x0 = Xs[b_loc * 3], x1 = Xs[b_loc * 3 + 1], x2 = Xs[b_loc * 3 + 2];
            const float* gr = &ghs[b_loc * 100];
#pragma unroll
            for (int j = 0; j < 8; j++) {
                int hh = h0 + j;
                float ghr = gr[hh];
                float ghz = gr[32 + hh];
                float ghn = gr[64 + hh];
                const float* wr = &wihs[(0 * 32 + hh) * 3];
                const float* wz = &wihs[(1 * 32 + hh) * 3];
                const float* wn = &wihs[(2 * 32 + hh) * 3];
                float gi_r = fmaf(x2, wr[2], fmaf(x1, wr[1], x0 * wr[0])) + bihs[hh];
                float gi_z = fmaf(x2, wz[2], fmaf(x1, wz[1], x0 * wz[0])) + bihs[32 + hh];
                float gi_n = fmaf(x2, wn[2], fmaf(x1, wn[1], x0 * wn[0])) + bihs[64 + hh];
                float r = sigf(gi_r + ghr + bhhs[hh]);
                float z = sigf(gi_z + ghz + bhhs[32 + hh]);
                float n = tanhf_fast(gi_n + r * (ghn + bhhs[64 + hh]));
                float hn = n + z * (hprev[j] - n);
                hprev[j] = hn;
                hf[j] = hn;
            }
            __half2 ph[4];
#pragma unroll
            for (int j = 0; j < 4; j++)
                ph[j] = __floats2half2_rn(hf[2 * j], hf[2 * j + 1]);
            phq = make_uint4(*(uint32_t*)&ph[0], *(uint32_t*)&ph[1],
                             *(uint32_t*)&ph[2], *(uint32_t*)&ph[3]);
            *(uint4*)&g_hx[t & 1][(size_t)bglob * HH + hb0 + h0] = phq;
        }

        // ---- barrier arrive, then non-critical stores overlap the spin ----
        __syncthreads();
        if (tid == 0) red_release_add(&g_barcnt[bg], 1u);
        {
            *(uint4*)&g_enc16[((size_t)bglob * TT + t) * HH + hb0 + h0] = phq;
            if (t == TT - 1) {
                float* hd = &g_h1[(size_t)bglob * HH + hb0 + h0];
                *(float4*)&hd[0] = make_float4(hf[0], hf[1], hf[2], hf[3]);
                *(float4*)&hd[4] = make_float4(hf[4], hf[5], hf[6], hf[7]);
            }
        }
        if (tid == 0) {
            unsigned target = 8u * (unsigned)(t + 1);
            while (ld_acq(&g_barcnt[bg]) < target) { }
        }
        __syncthreads();
    }
}

// ---------------- eproj: E16 = enc16 @ wte^T (64x64 tiles, k-pair packed) ----------------
__global__ __launch_bounds__(256) void eproj_kernel() {
    __shared__ __align__(16) u64 As[16 * 65];
    __shared__ __align__(16) u64 Ws[16 * 65];
    int tid = threadIdx.x;
    int m0 = blockIdx.x * 64, n0 = blockIdx.y * 64;
    int tx = tid & 15, ty = tid >> 4;

    u64 acc[4][4];
#pragma unroll
    for (int i = 0; i < 4; i++)
#pragma unroll
        for (int j = 0; j < 4; j++) acc[i][j] = 0ull;

    int sm = tid >> 2, sq = tid & 3;
    for (int k0 = 0; k0 < HH; k0 += 32) {
        __syncthreads();
        {
            float4 raw = *(const float4*)&g_enc16[(size_t)(m0 + sm) * HH + k0 + sq * 8];
            const __half2* h2 = (const __half2*)&raw;
#pragma unroll
            for (int p = 0; p < 4; p++) {
                float2 f = __half22float2(h2[p]);
                As[(sq * 4 + p) * 65 + sm] = pack2(f.x, f.y);
            }
#pragma unroll
            for (int p = 0; p < 4; p++) {
                float2 w2 = *(const float2*)&g_wte[(size_t)(n0 + sm) * HH + k0 + (sq * 4 + p) * 2];
                Ws[(sq * 4 + p) * 65 + sm] = pack2(w2.x, w2.y);
            }
        }
        __syncthreads();
#pragma unroll
        for (int kp = 0; kp < 16; kp++) {
            const u64* ap = &As[kp * 65 + ty * 4];
            const u64* wp = &Ws[kp * 65 + tx * 4];
            u64 a0 = ap[0], a1 = ap[1], a2 = ap[2], a3 = ap[3];
            u64 w0 = wp[0], w1 = wp[1], w2 = wp[2], w3 = wp[3];
            fma2(acc[0][0], a0, w0); fma2(acc[0][1], a0, w1); fma2(acc[0][2], a0, w2); fma2(acc[0][3], a0, w3);
            fma2(acc[1][0], a1, w0); fma2(acc[1][1], a1, w1); fma2(acc[1][2], a1, w2); fma2(acc[1][3], a1, w3);
            fma2(acc[2][0], a2, w0); fma2(acc[2][1], a2, w1); fma2(acc[2][2], a2, w2); fma2(acc[2][3], a2, w3);
            fma2(acc[3][0], a3, w0); fma2(acc[3][1], a3, w1); fma2(acc[3][2], a3, w2); fma2(acc[3][3], a3, w3);
        }
    }
#pragma unroll
    for (int i = 0; i < 4; i++) {
        int m = m0 + ty * 4 + i;
        float v[4];
#pragma unroll
        for (int j = 0; j < 4; j++) {
            float lo, hi; unpack2(acc[i][j], lo, hi);
            v[j] = lo + hi;
        }
        int n = n0 + tx * 4;
        *(__half2*)&g_eproj16[(size_t)m * HH + n]     = __floats2half2_rn(v[0], v[1]);
        *(__half2*)&g_eproj16[(size_t)m * HH + n + 2] = __floats2half2_rn(v[2], v[3]);
    }
}

// ---------------- dproj ----------------
__global__ __launch_bounds__(256) void dproj_kernel(const float* __restrict__ bt, int s) {
    const float* A = (s == 0) ? g_h1 : g_hd[s & 1];
    __shared__ __align__(16) float As[32][32];
    __shared__ __align__(16) float Ws[32][32];
    int tid = threadIdx.x;
    int m0 = blockIdx.x * 32, n0 = blockIdx.y * 32;
    int tx = tid & 15, ty = tid >> 4;
    u64 acc[2] = {0ull, 0ull};
    int lr = tid >> 3, lq = tid & 7;
    for (int k0 = 0; k0 < HH; k0 += 32) {
        __syncthreads();
        {
            float4 v = *(const float4*)&A[(size_t)(m0 + lr) * HH + k0 + lq * 4];
            As[lq * 4 + 0][lr] = v.x; As[lq * 4 + 1][lr] = v.y;
            As[lq * 4 + 2][lr] = v.z; As[lq * 4 + 3][lr] = v.w;
        }
        {
            float4 v = *(const float4*)&g_wtd[(size_t)(n0 + lr) * HH + k0 + lq * 4];
            Ws[lq * 4 + 0][lr] = v.x; Ws[lq * 4 + 1][lr] = v.y;
            Ws[lq * 4 + 2][lr] = v.z; Ws[lq * 4 + 3][lr] = v.w;
        }
        __syncthreads();
#pragma unroll
        for (int k = 0; k < 32; k++) {
            float2 a2 = *(const float2*)&As[k][ty * 2];
            u64 w = *(const u64*)&Ws[k][tx * 2];
            fma2(acc[0], pack2(a2.x, a2.x), w);
            fma2(acc[1], pack2(a2.y, a2.y), w);
        }
    }
#pragma unroll
    for (int i = 0; i < 2; i++) {
        float lo, hi; unpack2(acc[i], lo, hi);
        int m = m0 + ty * 2 + i, n = n0 + tx * 2;
        g_dproj[(size_t)m * HH + n] = lo + bt[n];
        g_dproj[(size_t)m * HH + n + 1] = hi + bt[n + 1];
    }
}

// ---------------- decoder temporal attention (fp16 streams + tanh.approx) ----------------
__global__ __launch_bounds__(256) void tscore_kernel(const float* __restrict__ vt) {
    int b = blockIdx.y;
    int tid = threadIdx.x;
    __shared__ float dps[HH], vts[HH];
    dps[tid] = g_dproj[(size_t)b * HH + tid];
    vts[tid] = vt[tid];
    __syncthreads();
    int w = tid >> 5, lane = tid & 31;
    int t = blockIdx.x * 8 + w;
    const __half2* row2 = (const __half2*)&g_eproj16[((size_t)b * TT + t) * HH];
    float s = 0.0f;
#pragma unroll
    for (int i = 0; i < 4; i++) {
        int j = lane + 32 * i;
        float2 c = __half22float2(row2[j]);
        s += tanh_apx(c.x + dps[2 * j]) * vts[2 * j];
        s += tanh_apx(c.y + dps[2 * j + 1]) * vts[2 * j + 1];
    }
    s = warp_sum(s);
    if (lane == 0) g_ts[(size_t)b * TT + t] = s;
}

__global__ __launch_bounds__(256) void softmax_t_kernel() {
    int b = blockIdx.x, tid = threadIdx.x;
    __shared__ float sm[256];
    float v = g_ts[(size_t)b * TT + tid];
    sm[tid] = v;
    __syncthreads();
    for (int o = 128; o > 0; o >>= 1) {
        if (tid < o) sm[tid] = fmaxf(sm[tid], sm[tid + o]);
        __syncthreads();
    }
    float m = sm[0];
    __syncthreads();
    float e = ex2f((v - m) * 1.4426950408889634f);
    sm[tid] = e;
    __syncthreads();
    for (int o = 128; o > 0; o >>= 1) {
        if (tid < o) sm[tid] += sm[tid + o];
        __syncthreads();
    }
    g_tw[(size_t)b * TT + tid] = e * frcp(sm[0]);
}

__global__ __launch_bounds__(128) void context_kernel() {
    int b = blockIdx.x, tid = threadIdx.x;   // tid = half2 col (h = 2tid, 2tid+1)
    __shared__ float tws[TT];
    tws[tid] = g_tw[(size_t)b * TT + tid];
    tws[tid + 128] = g_tw[(size_t)b * TT + tid + 128];
    __syncthreads();
    const __half2* base2 = (const __half2*)&g_enc16[(size_t)b * TT * HH] + tid;
    float a0 = 0.0f, a1 = 0.0f;
#pragma unroll 8
    for (int t = 0; t < TT; t++) {
        float2 c = __half22float2(base2[(size_t)t * (HH / 2)]);
        float w = tws[t];
        a0 = fmaf(w, c.x, a0);
        a1 = fmaf(w, c.y, a1);
    }
    g_inp[b * INPAD + OUTD + 2 * tid] = a0;
    g_inp[b * INPAD + OUTD + 2 * tid + 1] = a1;
}

// ---------------- decoder GRU step ----------------
template <int TGN>
__device__ __forceinline__ void gemm_gate_phase(
        u64 (&acc)[4][4],
        const float* __restrict__ Ain, int astr,
        const float* __restrict__ Wm, int wstr, int Ktot,
        int bm0, int hb0, int tid, int tx, int ty,
        float (&As)[16][64], float (&Ws)[3][16][32]) {
    int lr = tid >> 2, lq = tid & 3;
    for (int k0 = 0; k0 < Ktot; k0 += 16) {
        __syncthreads();
        {
            float4 v = *(const float4*)&Ain[(size_t)(bm0 + lr) * astr + k0 + lq * 4];
            As[lq * 4 + 0][lr] = v.x; As[lq * 4 + 1][lr] = v.y;
            As[lq * 4 + 2][lr] = v.z; As[lq * 4 + 3][lr] = v.w;
        }
        for (int i = tid; i < 384; i += 256) {
            int row = i >> 2, q = i & 3, g = row >> 5, hh = row & 31;
            float4 v = *(const float4*)&Wm[(size_t)(g * HH + hb0 + hh) * wstr + k0 + q * 4];
            Ws[g][q * 4 + 0][hh] = v.x; Ws[g][q * 4 + 1][hh] = v.y;
            Ws[g][q * 4 + 2][hh] = v.z; Ws[g][q * 4 + 3][hh] = v.w;
        }
        __syncthreads();
#pragma unroll
        for (int k = 0; k < 16; k++) {
            float4 a4 = *(const float4*)&As[k][ty * 4];
            u64 w0 = *(const u64*)&Ws[0][k][tx * 2];
            u64 w1 = *(const u64*)&Ws[1][k][tx * 2];
            u64 w2 = *(const u64*)&Ws[2][k][tx * 2];
            u64 a;
            a = pack2(a4.x, a4.x); fma2(acc[0][0], a, w0); fma2(acc[1][0], a, w1); fma2(acc[TGN][0], a, w2);
            a = pack2(a4.y, a4.y); fma2(acc[0][1], a, w0); fma2(acc[1][1], a, w1); fma2(acc[TGN][1], a, w2);
            a = pack2(a4.z, a4.z); fma2(acc[0][2], a, w0); fma2(acc[1][2], a, w1); fma2(acc[TGN][2], a, w2);
            a = pack2(a4.w, a4.w); fma2(acc[0][3], a, w0); fma2(acc[1][3], a, w1); fma2(acc[TGN][3], a, w2);
        }
    }
}

__global__ __launch_bounds__(256) void dec_gru_kernel(
        const float* __restrict__ Whh, const float* __restrict__ bih,
        const float* __restrict__ bhh, int s) {
    const float* hin = (s == 0) ? g_h1 : g_hd[s & 1];
    float* hout = g_hd[(s + 1) & 1];

    __shared__ __align__(16) float As[16][64];
    __shared__ __align__(16) float Ws[3][16][32];
    __shared__ float bihs[3][32], bhhs[3][32];

    int tid = threadIdx.x;
    int bm0 = blockIdx.x * 64, hb0 = blockIdx.y * 32;
    int tx = tid & 15, ty = tid >> 4;
    if (tid < 96) {
        int g = tid >> 5, hh = tid & 31;
        bihs[g][hh] = bih[g * HH + hb0 + hh];
        bhhs[g][hh] = bhh[g * HH + hb0 + hh];
    }

    u64 acc[4][4];
#pragma unroll
    for (int g = 0; g < 4; g++)
#pragma unroll
        for (int i = 0; i < 4; i++) acc[g][i] = 0ull;

    gemm_gate_phase<2>(acc, hin, HH, Whh, HH, HH, bm0, hb0, tid, tx, ty, As, Ws);
    gemm_gate_phase<3>(acc, g_inp, INPAD, g_wihp, INPAD, INPAD, bm0, hb0, tid, tx, ty, As, Ws);

#pragma unroll
    for (int i = 0; i < 4; i++) {
        int b = bm0 + ty * 4 + i;
        float2 hp = *(const float2*)&hin[(size_t)b * HH + hb0 + tx * 2];
        float a0[2], a1[2], a2[2], a3[2];
        unpack2(acc[0][i], a0[0], a0[1]);
        unpack2(acc[1][i], a1[0], a1[1]);
        unpack2(acc[2][i], a2[0], a2[1]);
        unpack2(acc[3][i], a3[0], a3[1]);
#pragma unroll
        for (int j = 0; j < 2; j++) {
            int hl = tx * 2 + j;
            float r = sigf(a0[j] + bihs[0][hl] + bhhs[0][hl]);
            float z = sigf(a1[j] + bihs[1][hl] + bhhs[1][hl]);
            float n = tanhf_fast((a3[j] + bihs[2][hl]) + r * (a2[j] + bhhs[2][hl]));
            float hprev = (j == 0) ? hp.x : hp.y;
            float hn = n + z * (hprev - n);
            hout[(size_t)b * HH + hb0 + hl] = hn;
        }
    }
}

// ---------------- prediction head ----------------
__global__ __launch_bounds__(288) void pred_kernel(
        const float* __restrict__ Wfc, const float* __restrict__ bfc,
        float* __restrict__ out, int s) {
    int b = blockIdx.x, tid = threadIdx.x;
    const float* h = &g_hd[(s + 1) & 1][(size_t)b * HH];
    __shared__ float hs[HH];
    if (tid < HH) hs[tid] = h[tid];
    __syncthreads();
    int w = tid >> 5, lane = tid & 31;
    float sacc = 0.0f;
#pragma unroll
    for (int i = 0; i < 8; i++) {
        int hh = lane + 32 * i;
        sacc += hs[hh] * Wfc[w * HH + hh];
    }
    sacc = warp_sum(sacc);
    if (lane == 0) {
        float p = sacc + bfc[w];
        out[((size_t)b * PL + s) * OUTD + w] = p;
        g_inp[b * INPAD + w] = p;
    }
}

// ---------------- host orchestration ----------------
extern "C" void kernel_launch(void* const* d_in, const int* in_sizes, int n_in,
                              void* d_out, int out_size) {
    const float* x    = (const float*)d_in[0];
    const float* Wa   = (const float*)d_in[1];
    const float* ba   = (const float*)d_in[2];
    const float* va   = (const float*)d_in[3];
    const float* eWih = (const float*)d_in[4];
    const float* eWhh = (const float*)d_in[5];
    const float* ebih = (const float*)d_in[6];
    const float* ebhh = (const float*)d_in[7];
    const float* dWih = (const float*)d_in[8];
    const float* dWhh = (const float*)d_in[9];
    const float* dbih = (const float*)d_in[10];
    const float* dbhh = (const float*)d_in[11];
    const float* Wt   = (const float*)d_in[12];
    const float* bt   = (const float*)d_in[13];
    const float* vt   = (const float*)d_in[14];
    const float* Wfc  = (const float*)d_in[15];
    const float* bfc  = (const float*)d_in[16];
    float* out = (float*)d_out;

    init_a_kernel<<<256, 256>>>(x);
    init_b_kernel<<<256, 256>>>(dWih, Wt);
    agent_attn_kernel<<<(BB * TT) / 8, 256>>>(x, Wa, ba, va);

    cudaFuncSetAttribute(enc_persistent,
                         cudaFuncAttributeMaxDynamicSharedMemorySize, ENC_SMEM);
    enc_persistent<<<128, 256, ENC_SMEM>>>(eWhh, eWih, ebih, ebhh);

    eproj_kernel<<<dim3((BB * TT) / 64, HH / 64), 256>>>();

    for (int s = 0; s < PL; s++) {
        dproj_kernel<<<dim3(BB / 32, HH / 32), 256>>>(bt, s);
        tscore_kernel<<<dim3(TT / 8, BB), 256>>>(vt);
        softmax_t_kernel<<<BB, 256>>>();
        context_kernel<<<BB, 128>>>();
        dec_gru_kernel<<<dim3(BB / 64, HH / 32), 256>>>(dWhh, dbih, dbhh, s);
        pred_kernel<<<BB, 288>>>(Wfc, bfc, out, s);
    }
}

// round 11
// speedup vs baseline: 2.6207x; 1.4654x over previous
#include <cuda_runtime.h>
#include <cuda_fp16.h>
#include <cstdint>

#define BB 1024
#define TT 256
#define HH 256
#define OUTD 9
#define PL 16
#define INPAD 272   // 9 + 256 = 265, padded to 272

typedef unsigned long long u64;

// ---------------- device scratch ----------------
__device__ __align__(16) float g_reprs[BB * TT * 3];
__device__ __align__(16) __half g_enc16[(size_t)BB * TT * HH];
__device__ __align__(16) __half g_eproj16[(size_t)BB * TT * HH];
__device__ __align__(16) __half g_hx[2][BB * HH];     // fp16 h exchange ping-pong
__device__ __align__(16) float g_h1[BB * HH];         // final encoder h (fp32)
__device__ __align__(16) float g_hd[2][BB * HH];
__device__ __align__(16) float g_dproj[BB * HH];
__device__ __align__(16) float g_inp[BB * INPAD];
__device__ __align__(16) float g_wihp[768 * INPAD];
__device__ __align__(16) float g_wtd[HH * HH];
__device__ __align__(16) __half g_wte16[HH * HH];
__device__ unsigned g_barcnt[16];

// ---------------- math helpers ----------------
__device__ __forceinline__ float ex2f(float x) {
    float r; asm("ex2.approx.f32 %0, %1;" : "=f"(r) : "f"(x)); return r;
}
__device__ __forceinline__ float frcp(float x) {
    float r; asm("rcp.approx.f32 %0, %1;" : "=f"(r) : "f"(x)); return r;
}
__device__ __forceinline__ float sigf(float x) {
    return frcp(1.0f + ex2f(-1.4426950408889634f * x));
}
__device__ __forceinline__ float tanhf_fast(float x) {
    float ax = fabsf(x);
    float e = ex2f(-2.8853900817779268f * ax);
    float r = (1.0f - e) * frcp(1.0f + e);
    return copysignf(r, x);
}
__device__ __forceinline__ float tanh_apx(float x) {
    float r; asm("tanh.approx.f32 %0, %1;" : "=f"(r) : "f"(x)); return r;
}
__device__ __forceinline__ u64 pack2(float lo, float hi) {
    u64 r;
    asm("mov.b64 %0, {%1, %2};" : "=l"(r)
        : "r"(__float_as_uint(lo)), "r"(__float_as_uint(hi)));
    return r;
}
__device__ __forceinline__ void unpack2(u64 v, float& lo, float& hi) {
    unsigned a, b;
    asm("mov.b64 {%0, %1}, %2;" : "=r"(a), "=r"(b) : "l"(v));
    lo = __uint_as_float(a); hi = __uint_as_float(b);
}
__device__ __forceinline__ void fma2(u64& d, u64 a, u64 b) {
    asm("fma.rn.f32x2 %0, %1, %2, %0;" : "+l"(d) : "l"(a), "l"(b));
}
__device__ __forceinline__ float warp_sum(float v) {
#pragma unroll
    for (int o = 16; o > 0; o >>= 1) v += __shfl_xor_sync(0xffffffffu, v, o);
    return v;
}
__device__ __forceinline__ unsigned ld_acq(const unsigned* p) {
    unsigned v;
    asm volatile("ld.acquire.gpu.u32 %0, [%1];" : "=r"(v) : "l"(p));
    return v;
}
__device__ __forceinline__ void red_release_add(unsigned* p, unsigned v) {
    asm volatile("red.release.gpu.global.add.u32 [%0], %1;" :: "l"(p), "r"(v) : "memory");
}
__device__ __forceinline__ uint32_t smem_u32(const void* p) {
    uint32_t a;
    asm("{ .reg .u64 t; cvta.to.shared.u64 t, %1; cvt.u32.u64 %0, t; }"
        : "=r"(a) : "l"(p));
    return a;
}
__device__ __forceinline__ void ldm4(uint32_t* r, uint32_t addr) {
    asm volatile("ldmatrix.sync.aligned.m8n8.x4.shared.b16 {%0,%1,%2,%3}, [%4];"
        : "=r"(r[0]), "=r"(r[1]), "=r"(r[2]), "=r"(r[3]) : "r"(addr));
}
__device__ __forceinline__ void mma16816(float* c,
        uint32_t a0, uint32_t a1, uint32_t a2, uint32_t a3,
        uint32_t b0, uint32_t b1) {
    asm volatile(
        "mma.sync.aligned.m16n8k16.row.col.f32.f16.f16.f32 "
        "{%0,%1,%2,%3}, {%4,%5,%6,%7}, {%8,%9}, {%0,%1,%2,%3};"
        : "+f"(c[0]), "+f"(c[1]), "+f"(c[2]), "+f"(c[3])
        : "r"(a0), "r"(a1), "r"(a2), "r"(a3), "r"(b0), "r"(b1));
}

// ---------------- init ----------------
__global__ void init_a_kernel(const float* __restrict__ x) {
    int idx = blockIdx.x * blockDim.x + threadIdx.x;
    int stride = gridDim.x * blockDim.x;
    if (idx < 16) g_barcnt[idx] = 0u;
    for (int i = idx; i < BB * INPAD; i += stride) {
        int b = i / INPAD, c = i - b * INPAD;
        g_inp[i] = (c < OUTD) ? x[((size_t)b * TT + (TT - 1)) * OUTD + c] : 0.0f;
    }
}
__global__ void init_b_kernel(const float* __restrict__ dWih,
                              const float* __restrict__ Wt) {
    int idx = blockIdx.x * blockDim.x + threadIdx.x;
    int stride = gridDim.x * blockDim.x;
    for (int i = idx; i < 768 * INPAD; i += stride) {
        int row = i / INPAD, c = i - row * INPAD;
        g_wihp[i] = (c < OUTD + HH) ? dWih[row * (OUTD + HH) + c] : 0.0f;
    }
    for (int i = idx; i < HH * HH; i += stride) {
        int g = i >> 8, c = i & 255;
        g_wtd[i] = Wt[g * (2 * HH) + c];
        g_wte16[i] = __float2half_rn(Wt[g * (2 * HH) + HH + c]);
    }
}

// ---------------- stage 1: agent attention ----------------
__global__ __launch_bounds__(256) void agent_attn_kernel(
        const float* __restrict__ x, const float* __restrict__ Wa,
        const float* __restrict__ ba, const float* __restrict__ va) {
    __shared__ float Was[HH * 3];
    __shared__ float vas[HH];
    __shared__ float bas[HH];
    int tid = threadIdx.x;
    for (int i = tid; i < HH * 3; i += 256) Was[i] = Wa[i];
    vas[tid] = va[tid];
    bas[tid] = ba[tid];
    __syncthreads();

    int pair = blockIdx.x * 8 + (tid >> 5);
    int lane = tid & 31;
    const float* xp = &x[(size_t)pair * 9];
    float xv[9];
#pragma unroll
    for (int i = 0; i < 9; i++) xv[i] = xp[i];

    float sc[3];
#pragma unroll
    for (int a = 0; a < 3; a++) {
        float s = 0.0f;
        float x0 = xv[a * 3], x1 = xv[a * 3 + 1], x2 = xv[a * 3 + 2];
#pragma unroll
        for (int i = 0; i < 8; i++) {
            int h = lane + 32 * i;
            float e = tanhf_fast(fmaf(x2, Was[h * 3 + 2],
                          fmaf(x1, Was[h * 3 + 1], x0 * Was[h * 3])) + bas[h]);
            s += e * vas[h];
        }
        sc[a] = warp_sum(s);
    }
    float m = fmaxf(sc[0], fmaxf(sc[1], sc[2]));
    float e0 = ex2f((sc[0] - m) * 1.4426950408889634f);
    float e1 = ex2f((sc[1] - m) * 1.4426950408889634f);
    float e2 = ex2f((sc[2] - m) * 1.4426950408889634f);
    float inv = frcp(e0 + e1 + e2);
    float a0 = e0 * inv, a1 = e1 * inv, a2 = e2 * inv;
    if (lane < 3) {
        g_reprs[pair * 3 + lane] =
            a0 * xv[lane] + a1 * xv[3 + lane] + a2 * xv[6 + lane];
    }
}

// ---------------- stage 2: mma.sync persistent encoder (R9/R10 config) ----------------
#define ROWB 528                          // padded row bytes (264 halves)
#define AHI_OFF 0
#define BHI_OFF (64 * ROWB)
#define GHS_OFF (BHI_OFF + 96 * ROWB)
#define XS_OFF  (GHS_OFF + 64 * 100 * 4)
#define WIH_OFF (XS_OFF + 192 * 4)
#define BIH_OFF (WIH_OFF + 288 * 4)
#define BHH_OFF (BIH_OFF + 96 * 4)
#define ENC_SMEM (BHH_OFF + 96 * 4)

__global__ __launch_bounds__(256, 1) void enc_persistent(
        const float* __restrict__ Whh, const float* __restrict__ Wih,
        const float* __restrict__ bih, const float* __restrict__ bhh) {
    extern __shared__ __align__(16) char smraw[];
    uint32_t smem_base = smem_u32(smraw);
    float* ghs  = (float*)(smraw + GHS_OFF);      // [64][100]
    float* Xs   = (float*)(smraw + XS_OFF);       // [64][3]
    float* wihs = (float*)(smraw + WIH_OFF);      // [3*32][3]
    float* bihs = (float*)(smraw + BIH_OFF);      // [96]
    float* bhhs = (float*)(smraw + BHH_OFF);      // [96]

    int tid = threadIdx.x;
    int wid = tid >> 5, lane = tid & 31;
    int bid = blockIdx.x;
    int bg  = bid >> 3;                // batch group 0..15
    int bm0 = bg * 64;
    int hb0 = (bid & 7) * 32;

    for (int i = tid; i < (64 * ROWB) / 16; i += 256)
        ((uint4*)smraw)[i] = make_uint4(0, 0, 0, 0);

    for (int i = tid; i < 96 * 128; i += 256) {
        int n = i >> 7, kp = i & 127;
        int g = n >> 5, hh = n & 31;
        float2 w = *(const float2*)&Whh[(size_t)(g * HH + hb0 + hh) * HH + kp * 2];
        *(__half2*)(smraw + BHI_OFF + n * ROWB + kp * 4) = __floats2half2_rn(w.x, w.y);
    }
    for (int i = tid; i < 288; i += 256) {
        int g = i / 96, r = i % 96, hh = r / 3, f = r % 3;
        wihs[(g * 32 + hh) * 3 + f] = Wih[(size_t)(g * HH + hb0 + hh) * 3 + f];
    }
    if (tid < 96) {
        int g = tid >> 5, hh = tid & 31;
        bihs[g * 32 + hh] = bih[g * HH + hb0 + hh];
        bhhs[g * 32 + hh] = bhh[g * HH + hb0 + hh];
    }
    __syncthreads();

    int mw = wid >> 1, nw = wid & 1;
    uint32_t a_off = (uint32_t)(((lane & 7) + ((lane >> 3) & 1) * 8) * ROWB
                                + ((lane >> 4) & 1) * 16);
    uint32_t b_off = (uint32_t)(((lane & 7) + ((lane >> 4) & 1) * 8) * ROWB
                                + ((lane >> 3) & 1) * 16);
    uint32_t Ah = smem_base + AHI_OFF + mw * 16 * ROWB + a_off;
    uint32_t Bh = smem_base + BHI_OFF + nw * 48 * ROWB + b_off;

    int b_loc = tid >> 2;
    int h0 = (tid & 3) * 8;
    int bglob = bm0 + b_loc;
    float hprev[8];
#pragma unroll
    for (int j = 0; j < 8; j++) hprev[j] = 0.0f;

    for (int t = 0; t < TT; t++) {
        if (t > 0) {
            const __half* hsrc = g_hx[(t + 1) & 1];
            for (int i = tid; i < 2048; i += 256) {
                int r = i >> 5, kc = i & 31;
                uint4 v = __ldcg((const uint4*)&hsrc[(size_t)(bm0 + r) * HH + kc * 8]);
                *(uint4*)(smraw + AHI_OFF + r * ROWB + kc * 16) = v;
            }
        }
        if (tid < 192) {
            int b = tid / 3, f = tid % 3;
            Xs[b * 3 + f] = g_reprs[((size_t)(bm0 + b) * TT + t) * 3 + f];
        }
        __syncthreads();

        float acc[6][4];
#pragma unroll
        for (int f = 0; f < 6; f++)
#pragma unroll
            for (int q = 0; q < 4; q++) acc[f][q] = 0.0f;

#pragma unroll 4
        for (int ks = 0; ks < 16; ks++) {
            uint32_t koff = ks * 32;
            uint32_t ah[4], bh[3][4];
            ldm4(ah, Ah + koff);
#pragma unroll
            for (int f = 0; f < 3; f++) ldm4(bh[f], Bh + f * 16 * ROWB + koff);
#pragma unroll
            for (int f = 0; f < 3; f++) {
                mma16816(acc[2 * f],     ah[0], ah[1], ah[2], ah[3], bh[f][0], bh[f][1]);
                mma16816(acc[2 * f + 1], ah[0], ah[1], ah[2], ah[3], bh[f][2], bh[f][3]);
            }
        }

        {
            int mrow = mw * 16 + (lane >> 2);
            int ncol = nw * 48 + 2 * (lane & 3);
#pragma unroll
            for (int bf = 0; bf < 3; bf++)
#pragma unroll
                for (int sub = 0; sub < 2; sub++) {
                    float* c = acc[bf * 2 + sub];
                    int n = ncol + bf * 16 + sub * 8;
                    *(float2*)&ghs[mrow * 100 + n] = make_float2(c[0], c[1]);
                    *(float2*)&ghs[(mrow + 8) * 100 + n] = make_float2(c[2], c[3]);
                }
        }
        __syncthreads();

        float hf[8];
        uint4 phq;
        {
            float x0 = Xs[b_loc * 3], x1 = Xs[b_loc * 3 + 1], x2 = Xs[b_loc * 3 + 2];
            const float* gr = &ghs[b_loc * 100];
#pragma unroll
            for (int j = 0; j < 8; j++) {
                int hh = h0 + j;
                float ghr = gr[hh];
                float ghz = gr[32 + hh];
                float ghn = gr[64 + hh];
                const float* wr = &wihs[(0 * 32 + hh) * 3];
                const float* wz = &wihs[(1 * 32 + hh) * 3];
                const float* wn = &wihs[(2 * 32 + hh) * 3];
                float gi_r = fmaf(x2, wr[2], fmaf(x1, wr[1], x0 * wr[0])) + bihs[hh];
                float gi_z = fmaf(x2, wz[2], fmaf(x1, wz[1], x0 * wz[0])) + bihs[32 + hh];
                float gi_n = fmaf(x2, wn[2], fmaf(x1, wn[1], x0 * wn[0])) + bihs[64 + hh];
                float r = sigf(gi_r + ghr + bhhs[hh]);
                float z = sigf(gi_z + ghz + bhhs[32 + hh]);
                float n = tanhf_fast(gi_n + r * (ghn + bhhs[64 + hh]));
                float hn = n + z * (hprev[j] - n);
                hprev[j] = hn;
                hf[j] = hn;
            }
            __half2 ph[4];
#pragma unroll
            for (int j = 0; j < 4; j++)
                ph[j] = __floats2half2_rn(hf[2 * j], hf[2 * j + 1]);
            phq = make_uint4(*(uint32_t*)&ph[0], *(uint32_t*)&ph[1],
                             *(uint32_t*)&ph[2], *(uint32_t*)&ph[3]);
            *(uint4*)&g_hx[t & 1][(size_t)bglob * HH + hb0 + h0] = phq;
        }

        __syncthreads();
        if (tid == 0) red_release_add(&g_barcnt[bg], 1u);
        {
            *(uint4*)&g_enc16[((size_t)bglob * TT + t) * HH + hb0 + h0] = phq;
            if (t == TT - 1) {
                float* hd = &g_h1[(size_t)bglob * HH + hb0 + h0];
                *(float4*)&hd[0] = make_float4(hf[0], hf[1], hf[2], hf[3]);
                *(float4*)&hd[4] = make_float4(hf[4], hf[5], hf[6], hf[7]);
            }
        }
        if (tid == 0) {
            unsigned target = 8u * (unsigned)(t + 1);
            while (ld_acq(&g_barcnt[bg]) < target) { }
        }
        __syncthreads();
    }
}

// ---------------- eproj via mma.sync: E16 = enc16 @ wte16^T ----------------
// 64x64 block tiles, 8 warps of 16x32, K=256 staged once.
#define EP_SMEM (2 * 64 * ROWB)

__global__ __launch_bounds__(256) void eproj_kernel() {
    extern __shared__ __align__(16) char sm[];
    uint32_t sb = smem_u32(sm);
    char* smA = sm;
    char* smB = sm + 64 * ROWB;
    int tid = threadIdx.x, wid = tid >> 5, lane = tid & 31;
    int m0 = blockIdx.x * 64, n0 = blockIdx.y * 64;

    for (int i = tid; i < 2048; i += 256) {
        int r = i >> 5, kc = i & 31;
        *(uint4*)(smA + r * ROWB + kc * 16) =
            *(const uint4*)&g_enc16[(size_t)(m0 + r) * HH + kc * 8];
        *(uint4*)(smB + r * ROWB + kc * 16) =
            *(const uint4*)&g_wte16[(size_t)(n0 + r) * HH + kc * 8];
    }
    __syncthreads();

    int mw = wid >> 1, nw = wid & 1;
    uint32_t a_off = (uint32_t)(((lane & 7) + ((lane >> 3) & 1) * 8) * ROWB
                                + ((lane >> 4) & 1) * 16);
    uint32_t b_off = (uint32_t)(((lane & 7) + ((lane >> 4) & 1) * 8) * ROWB
                                + ((lane >> 3) & 1) * 16);
    uint32_t Ah = sb + mw * 16 * ROWB + a_off;
    uint32_t Bh = sb + 64 * ROWB + nw * 32 * ROWB + b_off;

    float acc[4][4];
#pragma unroll
    for (int f = 0; f < 4; f++)
#pragma unroll
        for (int q = 0; q < 4; q++) acc[f][q] = 0.0f;

#pragma unroll 4
    for (int ks = 0; ks < 16; ks++) {
        uint32_t koff = ks * 32;
        uint32_t ah[4], bh[2][4];
        ldm4(ah, Ah + koff);
        ldm4(bh[0], Bh + koff);
        ldm4(bh[1], Bh + 16 * ROWB + koff);
#pragma unroll
        for (int f = 0; f < 2; f++) {
            mma16816(acc[2 * f],     ah[0], ah[1], ah[2], ah[3], bh[f][0], bh[f][1]);
            mma16816(acc[2 * f + 1], ah[0], ah[1], ah[2], ah[3], bh[f][2], bh[f][3]);
        }
    }

    int mrow = m0 + mw * 16 + (lane >> 2);
    int ncol = n0 + nw * 32 + 2 * (lane & 3);
#pragma unroll
    for (int f = 0; f < 2; f++)
#pragma unroll
        for (int sub = 0; sub < 2; sub++) {
            float* c = acc[2 * f + sub];
            int n = ncol + f * 16 + sub * 8;
            *(__half2*)&g_eproj16[(size_t)mrow * HH + n] =
                __floats2half2_rn(c[0], c[1]);
            *(__half2*)&g_eproj16[(size_t)(mrow + 8) * HH + n] =
                __floats2half2_rn(c[2], c[3]);
        }
}

// ---------------- dproj ----------------
__global__ __launch_bounds__(256) void dproj_kernel(const float* __restrict__ bt, int s) {
    const float* A = (s == 0) ? g_h1 : g_hd[s & 1];
    __shared__ __align__(16) float As[32][32];
    __shared__ __align__(16) float Ws[32][32];
    int tid = threadIdx.x;
    int m0 = blockIdx.x * 32, n0 = blockIdx.y * 32;
    int tx = tid & 15, ty = tid >> 4;
    u64 acc[2] = {0ull, 0ull};
    int lr = tid >> 3, lq = tid & 7;
    for (int k0 = 0; k0 < HH; k0 += 32) {
        __syncthreads();
        {
            float4 v = *(const float4*)&A[(size_t)(m0 + lr) * HH + k0 + lq * 4];
            As[lq * 4 + 0][lr] = v.x; As[lq * 4 + 1][lr] = v.y;
            As[lq * 4 + 2][lr] = v.z; As[lq * 4 + 3][lr] = v.w;
        }
        {
            float4 v = *(const float4*)&g_wtd[(size_t)(n0 + lr) * HH + k0 + lq * 4];
            Ws[lq * 4 + 0][lr] = v.x; Ws[lq * 4 + 1][lr] = v.y;
            Ws[lq * 4 + 2][lr] = v.z; Ws[lq * 4 + 3][lr] = v.w;
        }
        __syncthreads();
#pragma unroll
        for (int k = 0; k < 32; k++) {
            float2 a2 = *(const float2*)&As[k][ty * 2];
            u64 w = *(const u64*)&Ws[k][tx * 2];
            fma2(acc[0], pack2(a2.x, a2.x), w);
            fma2(acc[1], pack2(a2.y, a2.y), w);
        }
    }
#pragma unroll
    for (int i = 0; i < 2; i++) {
        float lo, hi; unpack2(acc[i], lo, hi);
        int m = m0 + ty * 2 + i, n = n0 + tx * 2;
        g_dproj[(size_t)m * HH + n] = lo + bt[n];
        g_dproj[(size_t)m * HH + n + 1] = hi + bt[n + 1];
    }
}

// ---------------- fused decoder attention: scores + softmax + context ----------------
// one block per batch row; all dependencies are within-b.
__global__ __launch_bounds__(256) void dec_attn_kernel(const float* __restrict__ vt) {
    int b = blockIdx.x, tid = threadIdx.x;
    __shared__ float dps[HH], vts[HH], tws[TT], red[256];
    dps[tid] = g_dproj[(size_t)b * HH + tid];
    vts[tid] = vt[tid];
    __syncthreads();

    int w = tid >> 5, lane = tid & 31;
    const __half2* ep = (const __half2*)&g_eproj16[(size_t)b * TT * HH];
#pragma unroll 1
    for (int tl = 0; tl < 32; tl++) {
        int t = tl * 8 + w;
        const __half2* row2 = ep + (size_t)t * (HH / 2);
        float s = 0.0f;
#pragma unroll
        for (int i = 0; i < 4; i++) {
            int j = lane + 32 * i;
            float2 c = __half22float2(row2[j]);
            s += tanh_apx(c.x + dps[2 * j]) * vts[2 * j];
            s += tanh_apx(c.y + dps[2 * j + 1]) * vts[2 * j + 1];
        }
        s = warp_sum(s);
        if (lane == 0) tws[t] = s;
    }
    __syncthreads();

    // softmax over 256 scores
    float v = tws[tid];
    red[tid] = v;
    __syncthreads();
    for (int o = 128; o > 0; o >>= 1) {
        if (tid < o) red[tid] = fmaxf(red[tid], red[tid + o]);
        __syncthreads();
    }
    float m = red[0];
    __syncthreads();
    float e = ex2f((v - m) * 1.4426950408889634f);
    red[tid] = e;
    __syncthreads();
    for (int o = 128; o > 0; o >>= 1) {
        if (tid < o) red[tid] += red[tid + o];
        __syncthreads();
    }
    float inv = frcp(red[0]);
    __syncthreads();
    tws[tid] = e * inv;
    __syncthreads();

    // context: 256 threads = 2 t-partitions x 128 half2 columns
    int part = tid >> 7, col = tid & 127;
    const __half2* base2 = (const __half2*)&g_enc16[(size_t)b * TT * HH] + col;
    float a0 = 0.0f, a1 = 0.0f;
    int t0 = part * 128;
#pragma unroll 8
    for (int t = t0; t < t0 + 128; t++) {
        float2 c = __half22float2(base2[(size_t)t * (HH / 2)]);
        float ww = tws[t];
        a0 = fmaf(ww, c.x, a0);
        a1 = fmaf(ww, c.y, a1);
    }
    red[tid] = a0;
    dps[tid] = a1;      // dps no longer needed
    __syncthreads();
    if (tid < 128) {
        float s0 = red[tid] + red[tid + 128];
        float s1 = dps[tid] + dps[tid + 128];
        g_inp[b * INPAD + OUTD + 2 * tid] = s0;
        g_inp[b * INPAD + OUTD + 2 * tid + 1] = s1;
    }
}

// ---------------- decoder GRU step ----------------
template <int TGN>
__device__ __forceinline__ void gemm_gate_phase(
        u64 (&acc)[4][4],
        const float* __restrict__ Ain, int astr,
        const float* __restrict__ Wm, int wstr, int Ktot,
        int bm0, int hb0, int tid, int tx, int ty,
        float (&As)[16][64], float (&Ws)[3][16][32]) {
    int lr = tid >> 2, lq = tid & 3;
    for (int k0 = 0; k0 < Ktot; k0 += 16) {
        __syncthreads();
        {
            float4 v = *(const float4*)&Ain[(size_t)(bm0 + lr) * astr + k0 + lq * 4];
            As[lq * 4 + 0][lr] = v.x; As[lq * 4 + 1][lr] = v.y;
            As[lq * 4 + 2][lr] = v.z; As[lq * 4 + 3][lr] = v.w;
        }
        for (int i = tid; i < 384; i += 256) {
            int row = i >> 2, q = i & 3, g = row >> 5, hh = row & 31;
            float4 v = *(const float4*)&Wm[(size_t)(g * HH + hb0 + hh) * wstr + k0 + q * 4];
            Ws[g][q * 4 + 0][hh] = v.x; Ws[g][q * 4 + 1][hh] = v.y;
            Ws[g][q * 4 + 2][hh] = v.z; Ws[g][q * 4 + 3][hh] = v.w;
        }
        __syncthreads();
#pragma unroll
        for (int k = 0; k < 16; k++) {
            float4 a4 = *(const float4*)&As[k][ty * 4];
            u64 w0 = *(const u64*)&Ws[0][k][tx * 2];
            u64 w1 = *(const u64*)&Ws[1][k][tx * 2];
            u64 w2 = *(const u64*)&Ws[2][k][tx * 2];
            u64 a;
            a = pack2(a4.x, a4.x); fma2(acc[0][0], a, w0); fma2(acc[1][0], a, w1); fma2(acc[TGN][0], a, w2);
            a = pack2(a4.y, a4.y); fma2(acc[0][1], a, w0); fma2(acc[1][1], a, w1); fma2(acc[TGN][1], a, w2);
            a = pack2(a4.z, a4.z); fma2(acc[0][2], a, w0); fma2(acc[1][2], a, w1); fma2(acc[TGN][2], a, w2);
            a = pack2(a4.w, a4.w); fma2(acc[0][3], a, w0); fma2(acc[1][3], a, w1); fma2(acc[TGN][3], a, w2);
        }
    }
}

__global__ __launch_bounds__(256) void dec_gru_kernel(
        const float* __restrict__ Whh, const float* __restrict__ bih,
        const float* __restrict__ bhh, int s) {
    const float* hin = (s == 0) ? g_h1 : g_hd[s & 1];
    float* hout = g_hd[(s + 1) & 1];

    __shared__ __align__(16) float As[16][64];
    __shared__ __align__(16) float Ws[3][16][32];
    __shared__ float bihs[3][32], bhhs[3][32];

    int tid = threadIdx.x;
    int bm0 = blockIdx.x * 64, hb0 = blockIdx.y * 32;
    int tx = tid & 15, ty = tid >> 4;
    if (tid < 96) {
        int g = tid >> 5, hh = tid & 31;
        bihs[g][hh] = bih[g * HH + hb0 + hh];
        bhhs[g][hh] = bhh[g * HH + hb0 + hh];
    }

    u64 acc[4][4];
#pragma unroll
    for (int g = 0; g < 4; g++)
#pragma unroll
        for (int i = 0; i < 4; i++) acc[g][i] = 0ull;

    gemm_gate_phase<2>(acc, hin, HH, Whh, HH, HH, bm0, hb0, tid, tx, ty, As, Ws);
    gemm_gate_phase<3>(acc, g_inp, INPAD, g_wihp, INPAD, INPAD, bm0, hb0, tid, tx, ty, As, Ws);

#pragma unroll
    for (int i = 0; i < 4; i++) {
        int b = bm0 + ty * 4 + i;
        float2 hp = *(const float2*)&hin[(size_t)b * HH + hb0 + tx * 2];
        float a0[2], a1[2], a2[2], a3[2];
        unpack2(acc[0][i], a0[0], a0[1]);
        unpack2(acc[1][i], a1[0], a1[1]);
        unpack2(acc[2][i], a2[0], a2[1]);
        unpack2(acc[3][i], a3[0], a3[1]);
#pragma unroll
        for (int j = 0; j < 2; j++) {
            int hl = tx * 2 + j;
            float r = sigf(a0[j] + bihs[0][hl] + bhhs[0][hl]);
            float z = sigf(a1[j] + bihs[1][hl] + bhhs[1][hl]);
            float n = tanhf_fast((a3[j] + bihs[2][hl]) + r * (a2[j] + bhhs[2][hl]));
            float hprev = (j == 0) ? hp.x : hp.y;
            float hn = n + z * (hprev - n);
            hout[(size_t)b * HH + hb0 + hl] = hn;
        }
    }
}

// ---------------- prediction head ----------------
__global__ __launch_bounds__(288) void pred_kernel(
        const float* __restrict__ Wfc, const float* __restrict__ bfc,
        float* __restrict__ out, int s) {
    int b = blockIdx.x, tid = threadIdx.x;
    const float* h = &g_hd[(s + 1) & 1][(size_t)b * HH];
    __shared__ float hs[HH];
    if (tid < HH) hs[tid] = h[tid];
    __syncthreads();
    int w = tid >> 5, lane = tid & 31;
    float sacc = 0.0f;
#pragma unroll
    for (int i = 0; i < 8; i++) {
        int hh = lane + 32 * i;
        sacc += hs[hh] * Wfc[w * HH + hh];
    }
    sacc = warp_sum(sacc);
    if (lane == 0) {
        float p = sacc + bfc[w];
        out[((size_t)b * PL + s) * OUTD + w] = p;
        g_inp[b * INPAD + w] = p;
    }
}

// ---------------- host orchestration ----------------
extern "C" void kernel_launch(void* const* d_in, const int* in_sizes, int n_in,
                              void* d_out, int out_size) {
    const float* x    = (const float*)d_in[0];
    const float* Wa   = (const float*)d_in[1];
    const float* ba   = (const float*)d_in[2];
    const float* va   = (const float*)d_in[3];
    const float* eWih = (const float*)d_in[4];
    const float* eWhh = (const float*)d_in[5];
    const float* ebih = (const float*)d_in[6];
    const float* ebhh = (const float*)d_in[7];
    const float* dWih = (const float*)d_in[8];
    const float* dWhh = (const float*)d_in[9];
    const float* dbih = (const float*)d_in[10];
    const float* dbhh = (const float*)d_in[11];
    const float* Wt   = (const float*)d_in[12];
    const float* bt   = (const float*)d_in[13];
    const float* vt   = (const float*)d_in[14];
    const float* Wfc  = (const float*)d_in[15];
    const float* bfc  = (const float*)d_in[16];
    float* out = (float*)d_out;

    init_a_kernel<<<256, 256>>>(x);
    init_b_kernel<<<256, 256>>>(dWih, Wt);
    agent_attn_kernel<<<(BB * TT) / 8, 256>>>(x, Wa, ba, va);

    cudaFuncSetAttribute(enc_persistent,
                         cudaFuncAttributeMaxDynamicSharedMemorySize, ENC_SMEM);
    enc_persistent<<<128, 256, ENC_SMEM>>>(eWhh, eWih, ebih, ebhh);

    cudaFuncSetAttribute(eproj_kernel,
                         cudaFuncAttributeMaxDynamicSharedMemorySize, EP_SMEM);
    eproj_kernel<<<dim3((BB * TT) / 64, HH / 64), 256, EP_SMEM>>>();

    for (int s = 0; s < PL; s++) {
        dproj_kernel<<<dim3(BB / 32, HH / 32), 256>>>(bt, s);
        dec_attn_kernel<<<BB, 256>>>(vt);
        dec_gru_kernel<<<dim3(BB / 64, HH / 32), 256>>>(dWhh, dbih, dbhh, s);
        pred_kernel<<<BB, 288>>>(Wfc, bfc, out, s);
    }
}

// round 12
// speedup vs baseline: 3.1253x; 1.1925x over previous
#include <cuda_runtime.h>
#include <cuda_fp16.h>
#include <cstdint>

#define BB 1024
#define TT 256
#define HH 256
#define OUTD 9
#define PL 16
#define INPAD 272   // 9 + 256 = 265, padded to 272

typedef unsigned long long u64;

// ---------------- device scratch ----------------
__device__ __align__(16) float g_reprs[BB * TT * 3];
__device__ __align__(16) __half g_enc16[(size_t)BB * TT * HH];
__device__ __align__(16) __half g_eproj16[(size_t)BB * TT * HH];
__device__ __align__(16) __half g_hx[2][BB * HH];     // fp16 h exchange ping-pong
__device__ __align__(16) float g_h1[BB * HH];         // final encoder h (fp32)
__device__ __align__(16) float g_hd[2][BB * HH];
__device__ __align__(16) float g_inp[BB * INPAD];
__device__ __align__(16) __half g_wtdT16[HH * HH];    // transposed Wt_dec fp16
__device__ __align__(16) __half g_wte16[HH * HH];
__device__ __align__(16) __half g_wgru16[8 * 128 * 528];  // [hg][128 rows][528 k]
__device__ unsigned g_barcnt[16];

// ---------------- math helpers ----------------
__device__ __forceinline__ float ex2f(float x) {
    float r; asm("ex2.approx.f32 %0, %1;" : "=f"(r) : "f"(x)); return r;
}
__device__ __forceinline__ float frcp(float x) {
    float r; asm("rcp.approx.f32 %0, %1;" : "=f"(r) : "f"(x)); return r;
}
__device__ __forceinline__ float sigf(float x) {
    return frcp(1.0f + ex2f(-1.4426950408889634f * x));
}
__device__ __forceinline__ float tanhf_fast(float x) {
    float ax = fabsf(x);
    float e = ex2f(-2.8853900817779268f * ax);
    float r = (1.0f - e) * frcp(1.0f + e);
    return copysignf(r, x);
}
__device__ __forceinline__ float tanh_apx(float x) {
    float r; asm("tanh.approx.f32 %0, %1;" : "=f"(r) : "f"(x)); return r;
}
__device__ __forceinline__ float warp_sum(float v) {
#pragma unroll
    for (int o = 16; o > 0; o >>= 1) v += __shfl_xor_sync(0xffffffffu, v, o);
    return v;
}
__device__ __forceinline__ unsigned ld_acq(const unsigned* p) {
    unsigned v;
    asm volatile("ld.acquire.gpu.u32 %0, [%1];" : "=r"(v) : "l"(p));
    return v;
}
__device__ __forceinline__ void red_release_add(unsigned* p, unsigned v) {
    asm volatile("red.release.gpu.global.add.u32 [%0], %1;" :: "l"(p), "r"(v) : "memory");
}
__device__ __forceinline__ uint32_t smem_u32(const void* p) {
    uint32_t a;
    asm("{ .reg .u64 t; cvta.to.shared.u64 t, %1; cvt.u32.u64 %0, t; }"
        : "=r"(a) : "l"(p));
    return a;
}
__device__ __forceinline__ void ldm4(uint32_t* r, uint32_t addr) {
    asm volatile("ldmatrix.sync.aligned.m8n8.x4.shared.b16 {%0,%1,%2,%3}, [%4];"
        : "=r"(r[0]), "=r"(r[1]), "=r"(r[2]), "=r"(r[3]) : "r"(addr));
}
__device__ __forceinline__ void mma16816(float* c,
        uint32_t a0, uint32_t a1, uint32_t a2, uint32_t a3,
        uint32_t b0, uint32_t b1) {
    asm volatile(
        "mma.sync.aligned.m16n8k16.row.col.f32.f16.f16.f32 "
        "{%0,%1,%2,%3}, {%4,%5,%6,%7}, {%8,%9}, {%0,%1,%2,%3};"
        : "+f"(c[0]), "+f"(c[1]), "+f"(c[2]), "+f"(c[3])
        : "r"(a0), "r"(a1), "r"(a2), "r"(a3), "r"(b0), "r"(b1));
}

// ---------------- init ----------------
__global__ void init_a_kernel(const float* __restrict__ x) {
    int idx = blockIdx.x * blockDim.x + threadIdx.x;
    int stride = gridDim.x * blockDim.x;
    if (idx < 16) g_barcnt[idx] = 0u;
    for (int i = idx; i < BB * INPAD; i += stride) {
        int b = i / INPAD, c = i - b * INPAD;
        g_inp[i] = (c < OUTD) ? x[((size_t)b * TT + (TT - 1)) * OUTD + c] : 0.0f;
    }
}
__global__ void init_b_kernel(const float* __restrict__ Wt) {
    int idx = blockIdx.x * blockDim.x + threadIdx.x;
    int stride = gridDim.x * blockDim.x;
    for (int i = idx; i < HH * HH; i += stride) {
        int k = i >> 8, n = i & 255;
        g_wtdT16[i] = __float2half_rn(Wt[n * (2 * HH) + k]);       // Wt_dec^T
        int g = i >> 8, c = i & 255;
        g_wte16[i] = __float2half_rn(Wt[g * (2 * HH) + HH + c]);
    }
}
// pack decoder GRU weights: [hg][row(128)][k(528)] fp16
// rows 0..31 r (Whh|Wih), 32..63 z (Whh|Wih), 64..95 n_hh (Whh|0), 96..127 n_ih (0|Wih)
__global__ void init_c_kernel(const float* __restrict__ dWih,
                              const float* __restrict__ dWhh) {
    int idx = blockIdx.x * blockDim.x + threadIdx.x;
    int stride = gridDim.x * blockDim.x;
    const int TOT = 8 * 128 * 528;
    for (int i = idx; i < TOT; i += stride) {
        int hg = i / (128 * 528);
        int rem = i - hg * (128 * 528);
        int row = rem / 528;
        int k = rem - row * 528;
        int cls = row >> 5, hh = row & 31;
        int gr = hg * 32 + hh;
        float v = 0.0f;
        if (cls == 0) {
            v = (k < 256) ? dWhh[(size_t)(0 * 256 + gr) * 256 + k]
                : ((k - 256 < 265) ? dWih[(size_t)(0 * 256 + gr) * 265 + (k - 256)] : 0.0f);
        } else if (cls == 1) {
            v = (k < 256) ? dWhh[(size_t)(1 * 256 + gr) * 256 + k]
                : ((k - 256 < 265) ? dWih[(size_t)(1 * 256 + gr) * 265 + (k - 256)] : 0.0f);
        } else if (cls == 2) {
            v = (k < 256) ? dWhh[(size_t)(2 * 256 + gr) * 256 + k] : 0.0f;
        } else {
            v = (k >= 256 && k - 256 < 265) ? dWih[(size_t)(2 * 256 + gr) * 265 + (k - 256)] : 0.0f;
        }
        g_wgru16[i] = __float2half_rn(v);
    }
}

// ---------------- stage 1: agent attention ----------------
__global__ __launch_bounds__(256) void agent_attn_kernel(
        const float* __restrict__ x, const float* __restrict__ Wa,
        const float* __restrict__ ba, const float* __restrict__ va) {
    __shared__ float Was[HH * 3];
    __shared__ float vas[HH];
    __shared__ float bas[HH];
    int tid = threadIdx.x;
    for (int i = tid; i < HH * 3; i += 256) Was[i] = Wa[i];
    vas[tid] = va[tid];
    bas[tid] = ba[tid];
    __syncthreads();

    int pair = blockIdx.x * 8 + (tid >> 5);
    int lane = tid & 31;
    const float* xp = &x[(size_t)pair * 9];
    float xv[9];
#pragma unroll
    for (int i = 0; i < 9; i++) xv[i] = xp[i];

    float sc[3];
#pragma unroll
    for (int a = 0; a < 3; a++) {
        float s = 0.0f;
        float x0 = xv[a * 3], x1 = xv[a * 3 + 1], x2 = xv[a * 3 + 2];
#pragma unroll
        for (int i = 0; i < 8; i++) {
            int h = lane + 32 * i;
            float e = tanhf_fast(fmaf(x2, Was[h * 3 + 2],
                          fmaf(x1, Was[h * 3 + 1], x0 * Was[h * 3])) + bas[h]);
            s += e * vas[h];
        }
        sc[a] = warp_sum(s);
    }
    float m = fmaxf(sc[0], fmaxf(sc[1], sc[2]));
    float e0 = ex2f((sc[0] - m) * 1.4426950408889634f);
    float e1 = ex2f((sc[1] - m) * 1.4426950408889634f);
    float e2 = ex2f((sc[2] - m) * 1.4426950408889634f);
    float inv = frcp(e0 + e1 + e2);
    float a0 = e0 * inv, a1 = e1 * inv, a2 = e2 * inv;
    if (lane < 3) {
        g_reprs[pair * 3 + lane] =
            a0 * xv[lane] + a1 * xv[3 + lane] + a2 * xv[6 + lane];
    }
}

// ---------------- stage 2: mma.sync persistent encoder (R9 config, unchanged) ----------------
#define ROWB 528
#define AHI_OFF 0
#define BHI_OFF (64 * ROWB)
#define GHS_OFF (BHI_OFF + 96 * ROWB)
#define XS_OFF  (GHS_OFF + 64 * 100 * 4)
#define WIH_OFF (XS_OFF + 192 * 4)
#define BIH_OFF (WIH_OFF + 288 * 4)
#define BHH_OFF (BIH_OFF + 96 * 4)
#define ENC_SMEM (BHH_OFF + 96 * 4)

__global__ __launch_bounds__(256, 1) void enc_persistent(
        const float* __restrict__ Whh, const float* __restrict__ Wih,
        const float* __restrict__ bih, const float* __restrict__ bhh) {
    extern __shared__ __align__(16) char smraw[];
    uint32_t smem_base = smem_u32(smraw);
    float* ghs  = (float*)(smraw + GHS_OFF);
    float* Xs   = (float*)(smraw + XS_OFF);
    float* wihs = (float*)(smraw + WIH_OFF);
    float* bihs = (float*)(smraw + BIH_OFF);
    float* bhhs = (float*)(smraw + BHH_OFF);

    int tid = threadIdx.x;
    int wid = tid >> 5, lane = tid & 31;
    int bid = blockIdx.x;
    int bg  = bid >> 3;
    int bm0 = bg * 64;
    int hb0 = (bid & 7) * 32;

    for (int i = tid; i < (64 * ROWB) / 16; i += 256)
        ((uint4*)smraw)[i] = make_uint4(0, 0, 0, 0);

    for (int i = tid; i < 96 * 128; i += 256) {
        int n = i >> 7, kp = i & 127;
        int g = n >> 5, hh = n & 31;
        float2 w = *(const float2*)&Whh[(size_t)(g * HH + hb0 + hh) * HH + kp * 2];
        *(__half2*)(smraw + BHI_OFF + n * ROWB + kp * 4) = __floats2half2_rn(w.x, w.y);
    }
    for (int i = tid; i < 288; i += 256) {
        int g = i / 96, r = i % 96, hh = r / 3, f = r % 3;
        wihs[(g * 32 + hh) * 3 + f] = Wih[(size_t)(g * HH + hb0 + hh) * 3 + f];
    }
    if (tid < 96) {
        int g = tid >> 5, hh = tid & 31;
        bihs[g * 32 + hh] = bih[g * HH + hb0 + hh];
        bhhs[g * 32 + hh] = bhh[g * HH + hb0 + hh];
    }
    __syncthreads();

    int mw = wid >> 1, nw = wid & 1;
    uint32_t a_off = (uint32_t)(((lane & 7) + ((lane >> 3) & 1) * 8) * ROWB
                                + ((lane >> 4) & 1) * 16);
    uint32_t b_off = (uint32_t)(((lane & 7) + ((lane >> 4) & 1) * 8) * ROWB
                                + ((lane >> 3) & 1) * 16);
    uint32_t Ah = smem_base + AHI_OFF + mw * 16 * ROWB + a_off;
    uint32_t Bh = smem_base + BHI_OFF + nw * 48 * ROWB + b_off;

    int b_loc = tid >> 2;
    int h0 = (tid & 3) * 8;
    int bglob = bm0 + b_loc;
    float hprev[8];
#pragma unroll
    for (int j = 0; j < 8; j++) hprev[j] = 0.0f;

    for (int t = 0; t < TT; t++) {
        if (t > 0) {
            const __half* hsrc = g_hx[(t + 1) & 1];
            for (int i = tid; i < 2048; i += 256) {
                int r = i >> 5, kc = i & 31;
                uint4 v = __ldcg((const uint4*)&hsrc[(size_t)(bm0 + r) * HH + kc * 8]);
                *(uint4*)(smraw + AHI_OFF + r * ROWB + kc * 16) = v;
            }
        }
        if (tid < 192) {
            int b = tid / 3, f = tid % 3;
            Xs[b * 3 + f] = g_reprs[((size_t)(bm0 + b) * TT + t) * 3 + f];
        }
        __syncthreads();

        float acc[6][4];
#pragma unroll
        for (int f = 0; f < 6; f++)
#pragma unroll
            for (int q = 0; q < 4; q++) acc[f][q] = 0.0f;

#pragma unroll 4
        for (int ks = 0; ks < 16; ks++) {
            uint32_t koff = ks * 32;
            uint32_t ah[4], bh[3][4];
            ldm4(ah, Ah + koff);
#pragma unroll
            for (int f = 0; f < 3; f++) ldm4(bh[f], Bh + f * 16 * ROWB + koff);
#pragma unroll
            for (int f = 0; f < 3; f++) {
                mma16816(acc[2 * f],     ah[0], ah[1], ah[2], ah[3], bh[f][0], bh[f][1]);
                mma16816(acc[2 * f + 1], ah[0], ah[1], ah[2], ah[3], bh[f][2], bh[f][3]);
            }
        }

        {
            int mrow = mw * 16 + (lane >> 2);
            int ncol = nw * 48 + 2 * (lane & 3);
#pragma unroll
            for (int bf = 0; bf < 3; bf++)
#pragma unroll
                for (int sub = 0; sub < 2; sub++) {
                    float* c = acc[bf * 2 + sub];
                    int n = ncol + bf * 16 + sub * 8;
                    *(float2*)&ghs[mrow * 100 + n] = make_float2(c[0], c[1]);
                    *(float2*)&ghs[(mrow + 8) * 100 + n] = make_float2(c[2], c[3]);
                }
        }
        __syncthreads();

        float hf[8];
        uint4 phq;
        {
            float x0 = Xs[b_loc * 3], x1 = Xs[b_loc * 3 + 1], x2 = Xs[b_loc * 3 + 2];
            const float* gr = &ghs[b_loc * 100];
#pragma unroll
            for (int j = 0; j < 8; j++) {
                int hh = h0 + j;
                float ghr = gr[hh];
                float ghz = gr[32 + hh];
                float ghn = gr[64 + hh];
                const float* wr = &wihs[(0 * 32 + hh) * 3];
                const float* wz = &wihs[(1 * 32 + hh) * 3];
                const float* wn = &wihs[(2 * 32 + hh) * 3];
                float gi_r = fmaf(x2, wr[2], fmaf(x1, wr[1], x0 * wr[0])) + bihs[hh];
                float gi_z = fmaf(x2, wz[2], fmaf(x1, wz[1], x0 * wz[0])) + bihs[32 + hh];
                float gi_n = fmaf(x2, wn[2], fmaf(x1, wn[1], x0 * wn[0])) + bihs[64 + hh];
                float r = sigf(gi_r + ghr + bhhs[hh]);
                float z = sigf(gi_z + ghz + bhhs[32 + hh]);
                float n = tanhf_fast(gi_n + r * (ghn + bhhs[64 + hh]));
                float hn = n + z * (hprev[j] - n);
                hprev[j] = hn;
                hf[j] = hn;
            }
            __half2 ph[4];
#pragma unroll
            for (int j = 0; j < 4; j++)
                ph[j] = __floats2half2_rn(hf[2 * j], hf[2 * j + 1]);
            phq = make_uint4(*(uint32_t*)&ph[0], *(uint32_t*)&ph[1],
                             *(uint32_t*)&ph[2], *(uint32_t*)&ph[3]);
            *(uint4*)&g_hx[t & 1][(size_t)bglob * HH + hb0 + h0] = phq;
        }

        __syncthreads();
        if (tid == 0) red_release_add(&g_barcnt[bg], 1u);
        {
            *(uint4*)&g_enc16[((size_t)bglob * TT + t) * HH + hb0 + h0] = phq;
            if (t == TT - 1) {
                float* hd = &g_h1[(size_t)bglob * HH + hb0 + h0];
                *(float4*)&hd[0] = make_float4(hf[0], hf[1], hf[2], hf[3]);
                *(float4*)&hd[4] = make_float4(hf[4], hf[5], hf[6], hf[7]);
            }
        }
        if (tid == 0) {
            unsigned target = 8u * (unsigned)(t + 1);
            while (ld_acq(&g_barcnt[bg]) < target) { }
        }
        __syncthreads();
    }
}

// ---------------- eproj via mma.sync (R11, unchanged) ----------------
#define EP_SMEM (2 * 64 * ROWB)

__global__ __launch_bounds__(256) void eproj_kernel() {
    extern __shared__ __align__(16) char sm[];
    uint32_t sb = smem_u32(sm);
    char* smA = sm;
    char* smB = sm + 64 * ROWB;
    int tid = threadIdx.x, wid = tid >> 5, lane = tid & 31;
    int m0 = blockIdx.x * 64, n0 = blockIdx.y * 64;

    for (int i = tid; i < 2048; i += 256) {
        int r = i >> 5, kc = i & 31;
        *(uint4*)(smA + r * ROWB + kc * 16) =
            *(const uint4*)&g_enc16[(size_t)(m0 + r) * HH + kc * 8];
        *(uint4*)(smB + r * ROWB + kc * 16) =
            *(const uint4*)&g_wte16[(size_t)(n0 + r) * HH + kc * 8];
    }
    __syncthreads();

    int mw = wid >> 1, nw = wid & 1;
    uint32_t a_off = (uint32_t)(((lane & 7) + ((lane >> 3) & 1) * 8) * ROWB
                                + ((lane >> 4) & 1) * 16);
    uint32_t b_off = (uint32_t)(((lane & 7) + ((lane >> 4) & 1) * 8) * ROWB
                                + ((lane >> 3) & 1) * 16);
    uint32_t Ah = sb + mw * 16 * ROWB + a_off;
    uint32_t Bh = sb + 64 * ROWB + nw * 32 * ROWB + b_off;

    float acc[4][4];
#pragma unroll
    for (int f = 0; f < 4; f++)
#pragma unroll
        for (int q = 0; q < 4; q++) acc[f][q] = 0.0f;

#pragma unroll 4
    for (int ks = 0; ks < 16; ks++) {
        uint32_t koff = ks * 32;
        uint32_t ah[4], bh[2][4];
        ldm4(ah, Ah + koff);
        ldm4(bh[0], Bh + koff);
        ldm4(bh[1], Bh + 16 * ROWB + koff);
#pragma unroll
        for (int f = 0; f < 2; f++) {
            mma16816(acc[2 * f],     ah[0], ah[1], ah[2], ah[3], bh[f][0], bh[f][1]);
            mma16816(acc[2 * f + 1], ah[0], ah[1], ah[2], ah[3], bh[f][2], bh[f][3]);
        }
    }

    int mrow = m0 + mw * 16 + (lane >> 2);
    int ncol = n0 + nw * 32 + 2 * (lane & 3);
#pragma unroll
    for (int f = 0; f < 2; f++)
#pragma unroll
        for (int sub = 0; sub < 2; sub++) {
            float* c = acc[2 * f + sub];
            int n = ncol + f * 16 + sub * 8;
            *(__half2*)&g_eproj16[(size_t)mrow * HH + n] =
                __floats2half2_rn(c[0], c[1]);
            *(__half2*)&g_eproj16[(size_t)(mrow + 8) * HH + n] =
                __floats2half2_rn(c[2], c[3]);
        }
}

// ---------------- fused decoder attention: pred(s-1) + dproj + scores + softmax + context ----------------
__global__ __launch_bounds__(256) void dec_attn2_kernel(
        const float* __restrict__ vt, const float* __restrict__ bt,
        const float* __restrict__ Wfc, const float* __restrict__ bfc,
        float* __restrict__ out, int s) {
    int b = blockIdx.x, tid = threadIdx.x;
    int wid = tid >> 5, lane = tid & 31;
    __shared__ float hs[HH], dps[HH], vts[HH], tws[TT], red[256];
    const float* hin = (s == 0) ? g_h1 : g_hd[s & 1];
    hs[tid] = hin[(size_t)b * HH + tid];
    vts[tid] = vt[tid];
    __syncthreads();

    // pred(s-1): 9 warp-dots over hs
    if (s > 0) {
        float p = 0.0f;
#pragma unroll
        for (int i = 0; i < 8; i++) {
            int k = lane + 32 * i;
            p += hs[k] * Wfc[(size_t)wid * HH + k];
        }
        p = warp_sum(p);
        if (lane == 0) {
            float pv = p + bfc[wid];
            out[((size_t)b * PL + (s - 1)) * OUTD + wid] = pv;
            g_inp[b * INPAD + wid] = pv;
        }
        if (wid == 0) {
            float p8 = 0.0f;
#pragma unroll
            for (int i = 0; i < 8; i++) {
                int k = lane + 32 * i;
                p8 += hs[k] * Wfc[(size_t)8 * HH + k];
            }
            p8 = warp_sum(p8);
            if (lane == 0) {
                float pv = p8 + bfc[8];
                out[((size_t)b * PL + (s - 1)) * OUTD + 8] = pv;
                g_inp[b * INPAD + 8] = pv;
            }
        }
    }

    // dproj: dps[n] = hs . WtdT[:, n] + bt[n]  (coalesced across threads)
    {
        float acc = 0.0f;
#pragma unroll 8
        for (int k = 0; k < HH; k++)
            acc = fmaf(hs[k], __half2float(g_wtdT16[(size_t)k * HH + tid]), acc);
        dps[tid] = acc + bt[tid];
    }
    __syncthreads();

    // scores
    const __half2* ep = (const __half2*)&g_eproj16[(size_t)b * TT * HH];
#pragma unroll 1
    for (int tl = 0; tl < 32; tl++) {
        int t = tl * 8 + wid;
        const __half2* row2 = ep + (size_t)t * (HH / 2);
        float sv = 0.0f;
#pragma unroll
        for (int i = 0; i < 4; i++) {
            int j = lane + 32 * i;
            float2 c = __half22float2(row2[j]);
            sv += tanh_apx(c.x + dps[2 * j]) * vts[2 * j];
            sv += tanh_apx(c.y + dps[2 * j + 1]) * vts[2 * j + 1];
        }
        sv = warp_sum(sv);
        if (lane == 0) tws[t] = sv;
    }
    __syncthreads();

    // softmax over 256
    float v = tws[tid];
    red[tid] = v;
    __syncthreads();
    for (int o = 128; o > 0; o >>= 1) {
        if (tid < o) red[tid] = fmaxf(red[tid], red[tid + o]);
        __syncthreads();
    }
    float m = red[0];
    __syncthreads();
    float e = ex2f((v - m) * 1.4426950408889634f);
    red[tid] = e;
    __syncthreads();
    for (int o = 128; o > 0; o >>= 1) {
        if (tid < o) red[tid] += red[tid + o];
        __syncthreads();
    }
    float inv = frcp(red[0]);
    __syncthreads();
    tws[tid] = e * inv;
    __syncthreads();

    // context: 2 t-partitions x 128 half2 cols
    int part = tid >> 7, col = tid & 127;
    const __half2* base2 = (const __half2*)&g_enc16[(size_t)b * TT * HH] + col;
    float a0 = 0.0f, a1 = 0.0f;
    int t0 = part * 128;
#pragma unroll 8
    for (int t = t0; t < t0 + 128; t++) {
        float2 c = __half22float2(base2[(size_t)t * (HH / 2)]);
        float ww = tws[t];
        a0 = fmaf(ww, c.x, a0);
        a1 = fmaf(ww, c.y, a1);
    }
    red[tid] = a0;
    hs[tid] = a1;
    __syncthreads();
    if (tid < 128) {
        g_inp[b * INPAD + OUTD + 2 * tid] = red[tid] + red[tid + 128];
        g_inp[b * INPAD + OUTD + 2 * tid + 1] = hs[tid] + hs[tid + 128];
    }
}

// ---------------- decoder GRU via mma.sync ----------------
// grid (16,8): 64 batch rows x 32 h. N=128 weight rows {r, z, n_hh, n_ih}, K=528.
#define ROWB2 1088
#define GA_OFF 0
#define GB_OFF (64 * ROWB2)                 // 69632
#define GBI_OFF (GB_OFF + 128 * ROWB2)      // 208896
#define GRU_SMEM (GBI_OFF + 128 * 4)        // 209408

__global__ __launch_bounds__(256, 1) void dec_gru_mma(
        const float* __restrict__ bih, const float* __restrict__ bhh, int s) {
    extern __shared__ __align__(16) char sm[];
    uint32_t sb = smem_u32(sm);
    float* ghs = (float*)(sm + GA_OFF);      // overlays A after MMA: [64][132]
    float* bia = (float*)(sm + GBI_OFF);     // [4][32]: r(bih+bhh), z(bih+bhh), bih_n, bhh_n

    int tid = threadIdx.x;
    int wid = tid >> 5, lane = tid & 31;
    int bm0 = blockIdx.x * 64;
    int hg = blockIdx.y;
    int hb0 = hg * 32;

    const float* hin = (s == 0) ? g_h1 : g_hd[s & 1];
    float* hout = g_hd[(s + 1) & 1];

    if (tid < 32) {
        bia[tid]      = bih[0 * 256 + hb0 + tid] + bhh[0 * 256 + hb0 + tid];
        bia[32 + tid] = bih[1 * 256 + hb0 + tid] + bhh[1 * 256 + hb0 + tid];
        bia[64 + tid] = bih[2 * 256 + hb0 + tid];
        bia[96 + tid] = bhh[2 * 256 + hb0 + tid];
    }

    // stage B: 128 rows x 66 chunks of 8 halves
    const __half* wsrc = &g_wgru16[(size_t)hg * 128 * 528];
    for (int i = tid; i < 128 * 66; i += 256) {
        int row = i / 66, c = i - row * 66;
        *(uint4*)(sm + GB_OFF + row * ROWB2 + c * 16) =
            *(const uint4*)&wsrc[(size_t)row * 528 + c * 8];
    }
    // stage A: 64 rows x 66 chunks; k<256 from hin, else from g_inp
    for (int i = tid; i < 64 * 66; i += 256) {
        int row = i / 66, c = i - row * 66;
        float f[8];
        if (c < 32) {
            const float* src = &hin[(size_t)(bm0 + row) * HH + c * 8];
#pragma unroll
            for (int q = 0; q < 8; q++) f[q] = src[q];
        } else {
            const float* src = &g_inp[(size_t)(bm0 + row) * INPAD + (c - 32) * 8];
#pragma unroll
            for (int q = 0; q < 8; q++) f[q] = src[q];
        }
        __half2 h2[4];
#pragma unroll
        for (int q = 0; q < 4; q++) h2[q] = __floats2half2_rn(f[2 * q], f[2 * q + 1]);
        *(uint4*)(sm + GA_OFF + row * ROWB2 + c * 16) =
            make_uint4(*(uint32_t*)&h2[0], *(uint32_t*)&h2[1],
                       *(uint32_t*)&h2[2], *(uint32_t*)&h2[3]);
    }
    __syncthreads();

    // MMA: warp (mw 0..3: m=16, nw 0..1: n=64)
    int mw = wid >> 1, nw = wid & 1;
    uint32_t a_off = (uint32_t)(((lane & 7) + ((lane >> 3) & 1) * 8) * ROWB2
                                + ((lane >> 4) & 1) * 16);
    uint32_t b_off = (uint32_t)(((lane & 7) + ((lane >> 4) & 1) * 8) * ROWB2
                                + ((lane >> 3) & 1) * 16);
    uint32_t Ah = sb + GA_OFF + mw * 16 * ROWB2 + a_off;
    uint32_t Bh = sb + GB_OFF + nw * 64 * ROWB2 + b_off;

    float acc[8][4];
#pragma unroll
    for (int f = 0; f < 8; f++)
#pragma unroll
        for (int q = 0; q < 4; q++) acc[f][q] = 0.0f;

#pragma unroll 3
    for (int ks = 0; ks < 33; ks++) {
        uint32_t koff = ks * 32;
        uint32_t ah[4], bh[4][4];
        ldm4(ah, Ah + koff);
#pragma unroll
        for (int f = 0; f < 4; f++) ldm4(bh[f], Bh + f * 16 * ROWB2 + koff);
#pragma unroll
        for (int f = 0; f < 4; f++) {
            mma16816(acc[2 * f],     ah[0], ah[1], ah[2], ah[3], bh[f][0], bh[f][1]);
            mma16816(acc[2 * f + 1], ah[0], ah[1], ah[2], ah[3], bh[f][2], bh[f][3]);
        }
    }
    __syncthreads();   // A reads done; reuse region for ghs

    {
        int mrow = mw * 16 + (lane >> 2);
        int ncol = nw * 64 + 2 * (lane & 3);
#pragma unroll
        for (int f = 0; f < 4; f++)
#pragma unroll
            for (int sub = 0; sub < 2; sub++) {
                float* c = acc[2 * f + sub];
                int n = ncol + f * 16 + sub * 8;
                *(float2*)&ghs[mrow * 132 + n] = make_float2(c[0], c[1]);
                *(float2*)&ghs[(mrow + 8) * 132 + n] = make_float2(c[2], c[3]);
            }
    }
    __syncthreads();

    // epilogue: thread = (b_loc, 8 h)
    int b_loc = tid >> 2;
    int h0 = (tid & 3) * 8;
    int b = bm0 + b_loc;
    const float* gr = &ghs[b_loc * 132];
#pragma unroll
    for (int j = 0; j < 8; j++) {
        int hh = h0 + j;
        float r = sigf(gr[hh] + bia[hh]);
        float z = sigf(gr[32 + hh] + bia[32 + hh]);
        float n = tanhf_fast(gr[96 + hh] + bia[64 + hh] + r * (gr[64 + hh] + bia[96 + hh]));
        float hp = hin[(size_t)b * HH + hb0 + hh];
        hout[(size_t)b * HH + hb0 + hh] = n + z * (hp - n);
    }
}

// ---------------- final prediction head ----------------
__global__ __launch_bounds__(288) void pred_kernel(
        const float* __restrict__ Wfc, const float* __restrict__ bfc,
        float* __restrict__ out, int s) {
    int b = blockIdx.x, tid = threadIdx.x;
    const float* h = &g_hd[(s + 1) & 1][(size_t)b * HH];
    __shared__ float hs[HH];
    if (tid < HH) hs[tid] = h[tid];
    __syncthreads();
    int w = tid >> 5, lane = tid & 31;
    float sacc = 0.0f;
#pragma unroll
    for (int i = 0; i < 8; i++) {
        int hh = lane + 32 * i;
        sacc += hs[hh] * Wfc[w * HH + hh];
    }
    sacc = warp_sum(sacc);
    if (lane == 0) {
        out[((size_t)b * PL + s) * OUTD + w] = sacc + bfc[w];
    }
}

// ---------------- host orchestration ----------------
extern "C" void kernel_launch(void* const* d_in, const int* in_sizes, int n_in,
                              void* d_out, int out_size) {
    const float* x    = (const float*)d_in[0];
    const float* Wa   = (const float*)d_in[1];
    const float* ba   = (const float*)d_in[2];
    const float* va   = (const float*)d_in[3];
    const float* eWih = (const float*)d_in[4];
    const float* eWhh = (const float*)d_in[5];
    const float* ebih = (const float*)d_in[6];
    const float* ebhh = (const float*)d_in[7];
    const float* dWih = (const float*)d_in[8];
    const float* dWhh = (const float*)d_in[9];
    const float* dbih = (const float*)d_in[10];
    const float* dbhh = (const float*)d_in[11];
    const float* Wt   = (const float*)d_in[12];
    const float* bt   = (const float*)d_in[13];
    const float* vt   = (const float*)d_in[14];
    const float* Wfc  = (const float*)d_in[15];
    const float* bfc  = (const float*)d_in[16];
    float* out = (float*)d_out;

    init_a_kernel<<<256, 256>>>(x);
    init_b_kernel<<<256, 256>>>(Wt);
    init_c_kernel<<<256, 256>>>(dWih, dWhh);
    agent_attn_kernel<<<(BB * TT) / 8, 256>>>(x, Wa, ba, va);

    cudaFuncSetAttribute(enc_persistent,
                         cudaFuncAttributeMaxDynamicSharedMemorySize, ENC_SMEM);
    enc_persistent<<<128, 256, ENC_SMEM>>>(eWhh, eWih, ebih, ebhh);

    cudaFuncSetAttribute(eproj_kernel,
                         cudaFuncAttributeMaxDynamicSharedMemorySize, EP_SMEM);
    eproj_kernel<<<dim3((BB * TT) / 64, HH / 64), 256, EP_SMEM>>>();

    cudaFuncSetAttribute(dec_gru_mma,
                         cudaFuncAttributeMaxDynamicSharedMemorySize, GRU_SMEM);
    for (int s = 0; s < PL; s++) {
        dec_attn2_kernel<<<BB, 256>>>(vt, bt, Wfc, bfc, out, s);
        dec_gru_mma<<<dim3(16, 8), 256, GRU_SMEM>>>(dbih, dbhh, s);
    }
    pred_kernel<<<BB, 288>>>(Wfc, bfc, out, PL - 1);
}